// round 1
// baseline (speedup 1.0000x reference)
#include <cuda_runtime.h>
#include <cstdint>

#define MM   100000   // simplices
#define NF   128      // B * C_IN features per simplex
#define NOUT 64
#define KTOT 5        // [x, Ll x, Ll^2 x, Lu x, Lu^2 x]

// ---------------- scratch (device globals: no allocations allowed) ----------
__device__ float g_xt [(size_t)MM * NF];
__device__ float g_p1l[(size_t)MM * NF];
__device__ float g_p2l[(size_t)MM * NF];
__device__ float g_p1u[(size_t)MM * NF];
__device__ float g_p2u[(size_t)MM * NF];
__device__ float g_w  [KTOT * 64 * 64];   // Wt[j][o], j = k*64 + c

// ---------------- packed fp32x2 helpers (sm_100+) ---------------------------
__device__ __forceinline__ unsigned long long pack2_dup(float v) {
    unsigned long long r; uint32_t u = __float_as_uint(v);
    asm("mov.b64 %0, {%1,%2};" : "=l"(r) : "r"(u), "r"(u));
    return r;
}
__device__ __forceinline__ unsigned long long fma2(unsigned long long a,
                                                   unsigned long long b,
                                                   unsigned long long c) {
    unsigned long long d;
    asm("fma.rn.f32x2 %0, %1, %2, %3;" : "=l"(d) : "l"(a), "l"(b), "l"(c));
    return d;
}
__device__ __forceinline__ void unpack2(unsigned long long v, float& lo, float& hi) {
    uint32_t a, b;
    asm("mov.b64 {%0,%1}, %2;" : "=r"(a), "=r"(b) : "l"(v));
    lo = __uint_as_float(a); hi = __uint_as_float(b);
}

// ---------------- 1) transpose x (128, M) -> xt (M, 128) --------------------
// M = 100000 = 32*3125 exactly, 128 = 32*4 exactly: no guards needed.
__global__ void transpose_kernel(const float* __restrict__ x, float* __restrict__ xt) {
    __shared__ float tile[32][33];
    int mBase = blockIdx.x * 32, fBase = blockIdx.y * 32;
    int tx = threadIdx.x, ty = threadIdx.y;
#pragma unroll
    for (int i = 0; i < 32; i += 8)
        tile[ty + i][tx] = x[(size_t)(fBase + ty + i) * MM + mBase + tx];
    __syncthreads();
#pragma unroll
    for (int i = 0; i < 32; i += 8)
        xt[(size_t)(mBase + ty + i) * NF + fBase + tx] = tile[tx][ty + i];
}

// ---------------- 2) COO SpMM: out[r,:] += v * in[c,:] ----------------------
// One warp per nnz; each lane owns a float4 of the 128-feature row.
__global__ void spmm_kernel(const int* __restrict__ rows, const int* __restrict__ cols,
                            const float* __restrict__ vals,
                            const float* __restrict__ in, float* __restrict__ out,
                            int nnz) {
    int gid = blockIdx.x * blockDim.x + threadIdx.x;
    int e = gid >> 5;
    if (e >= nnz) return;
    int q = gid & 31;
    int r = rows[e];
    int c = cols[e];
    float v = vals[e];
    float4 s = *reinterpret_cast<const float4*>(in + (size_t)c * NF + q * 4);
    float a0 = v * s.x, a1 = v * s.y, a2 = v * s.z, a3 = v * s.w;
    float* dst = out + (size_t)r * NF + q * 4;
    asm volatile("red.global.add.v4.f32 [%0], {%1,%2,%3,%4};"
                 :: "l"(dst), "f"(a0), "f"(a1), "f"(a2), "f"(a3) : "memory");
}

// ---------------- 3) fold theta -> Wt[j][o] ---------------------------------
// k=0 -> theta[:,:,0] + theta[:,:,3] (x appears in both power stacks)
__global__ void wprep_kernel(const float* __restrict__ theta, float* __restrict__ w) {
    int i = blockIdx.x * blockDim.x + threadIdx.x;   // i = (k*64+c)*64 + o
    if (i >= KTOT * 64 * 64) return;
    int o = i & 63;
    int c = (i >> 6) & 63;
    int k = i >> 12;
    const int kmap[KTOT] = {0, 1, 2, 4, 5};
    float v = theta[(o * 64 + c) * 6 + kmap[k]];
    if (k == 0) v += theta[(o * 64 + c) * 6 + 3];
    w[i] = v;
}

// ---------------- 4) combine: y[b,o,m] = sum_j Wt[j][o] * U[j][(b,m)] -------
// One thread per (b, m). 32 packed f32x2 accumulators = all 64 outputs.
// smem: ws (320*64 f) + us tile (256 m x 64 c, pad 65) = 148480 B.
#define CMB_SMEM_FLOATS (KTOT * 64 * 64 + 256 * 65)
#define CMB_SMEM_BYTES  (CMB_SMEM_FLOATS * 4)

__global__ __launch_bounds__(256, 1)
void combine_kernel(const float* __restrict__ bias, float* __restrict__ y) {
    extern __shared__ float smem[];
    float* ws = smem;                       // [320][64]
    float* us = smem + KTOT * 64 * 64;      // [256][65]

    int t = threadIdx.x;
    int b = blockIdx.y;
    int mBase = blockIdx.x * 256;
    int m = mBase + t;

    for (int i = t; i < KTOT * 64 * 64; i += 256) ws[i] = g_w[i];

    unsigned long long acc[32];
#pragma unroll
    for (int p = 0; p < 32; p++) acc[p] = 0ull;

    const float* bufs[KTOT] = {g_xt, g_p1l, g_p2l, g_p1u, g_p2u};

    for (int k = 0; k < KTOT; k++) {
        __syncthreads();                    // protect previous us tile
        const float* src = bufs[k];
        // stage 256 m-rows x 64 channels (coalesced 256B runs along c)
        for (int i = t; i < 256 * 64; i += 256) {
            int ml = i >> 6, c = i & 63;
            int mm = mBase + ml;
            us[ml * 65 + c] = (mm < MM) ? src[(size_t)mm * NF + b * 64 + c] : 0.0f;
        }
        __syncthreads();
        if (m < MM) {
            const float* wk = ws + k * 64 * 64;
#pragma unroll 4
            for (int jc = 0; jc < 64; jc++) {
                unsigned long long u2 = pack2_dup(us[t * 65 + jc]);
                const ulonglong2* wv =
                    reinterpret_cast<const ulonglong2*>(wk + jc * 64);
#pragma unroll
                for (int q = 0; q < 16; q++) {
                    ulonglong2 wq = wv[q];          // pairs (w[4q],w[4q+1]),(w[4q+2],w[4q+3])
                    acc[2 * q]     = fma2(wq.x, u2, acc[2 * q]);
                    acc[2 * q + 1] = fma2(wq.y, u2, acc[2 * q + 1]);
                }
            }
        }
    }

    if (m < MM) {
#pragma unroll
        for (int q = 0; q < 16; q++) {
            float v0, v1, v2, v3;
            unpack2(acc[2 * q], v0, v1);
            unpack2(acc[2 * q + 1], v2, v3);
            int o = 4 * q;
            y[((size_t)b * 64 + o    ) * MM + m] = v0 + bias[o];
            y[((size_t)b * 64 + o + 1) * MM + m] = v1 + bias[o + 1];
            y[((size_t)b * 64 + o + 2) * MM + m] = v2 + bias[o + 2];
            y[((size_t)b * 64 + o + 3) * MM + m] = v3 + bias[o + 3];
        }
    }
}

// ---------------- launch ----------------------------------------------------
extern "C" void kernel_launch(void* const* d_in, const int* in_sizes, int n_in,
                              void* d_out, int out_size) {
    const int*   LlI  = (const int*)  d_in[0];   // (2, NNZ): rows then cols
    const float* LlV  = (const float*)d_in[1];
    const int*   LuI  = (const int*)  d_in[2];
    const float* LuV  = (const float*)d_in[3];
    const float* x    = (const float*)d_in[4];
    const float* th   = (const float*)d_in[5];
    const float* bias = (const float*)d_in[6];
    float*       y    = (float*)d_out;
    int nnz = in_sizes[1];                       // Ll_values element count

    float *xt, *p1l, *p2l, *p1u, *p2u, *w;
    cudaGetSymbolAddress((void**)&xt,  g_xt);
    cudaGetSymbolAddress((void**)&p1l, g_p1l);
    cudaGetSymbolAddress((void**)&p2l, g_p2l);
    cudaGetSymbolAddress((void**)&p1u, g_p1u);
    cudaGetSymbolAddress((void**)&p2u, g_p2u);
    cudaGetSymbolAddress((void**)&w,   g_w);

    size_t bufBytes = (size_t)MM * NF * sizeof(float);
    cudaMemsetAsync(p1l, 0, bufBytes);
    cudaMemsetAsync(p2l, 0, bufBytes);
    cudaMemsetAsync(p1u, 0, bufBytes);
    cudaMemsetAsync(p2u, 0, bufBytes);

    transpose_kernel<<<dim3(MM / 32, NF / 32), dim3(32, 8)>>>(x, xt);
    wprep_kernel<<<(KTOT * 64 * 64 + 255) / 256, 256>>>(th, w);

    int spmmBlocks = (int)(((long long)nnz * 32 + 255) / 256);
    spmm_kernel<<<spmmBlocks, 256>>>(LlI, LlI + nnz, LlV, xt,  p1l, nnz);
    spmm_kernel<<<spmmBlocks, 256>>>(LlI, LlI + nnz, LlV, p1l, p2l, nnz);
    spmm_kernel<<<spmmBlocks, 256>>>(LuI, LuI + nnz, LuV, xt,  p1u, nnz);
    spmm_kernel<<<spmmBlocks, 256>>>(LuI, LuI + nnz, LuV, p1u, p2u, nnz);

    cudaFuncSetAttribute(combine_kernel,
                         cudaFuncAttributeMaxDynamicSharedMemorySize, CMB_SMEM_BYTES);
    combine_kernel<<<dim3((MM + 255) / 256, 2), 256, CMB_SMEM_BYTES>>>(bias, y);
}

// round 2
// speedup vs baseline: 1.3934x; 1.3934x over previous
#include <cuda_runtime.h>
#include <cstdint>

#define MM    100000   // simplices
#define NF    128      // B * C_IN features per simplex
#define KTOT  5        // [x, Ll x, Ll^2 x, Lu x, Lu^2 x]
#define NNZCAP 800000

// ---------------- scratch (device globals: no allocations allowed) ----------
__device__ float g_xt [(size_t)MM * NF];
__device__ float g_p1l[(size_t)MM * NF];
__device__ float g_p2l[(size_t)MM * NF];
__device__ float g_p1u[(size_t)MM * NF];
__device__ float g_p2u[(size_t)MM * NF];
__device__ float g_w  [KTOT * 64 * 64];        // Wt[j][o], j = k*64 + c

// CSR build scratch (2 matrices)
__device__ int  g_cnt [2][MM];
__device__ int  g_rs  [2][MM + 1];
__device__ int  g_bsum[2][128];
__device__ int  g_pos [2][NNZCAP];
__device__ int2 g_ents[2][NNZCAP];             // {col, val_bits} grouped by row

// ---------------- packed fp32x2 helpers (sm_100+) ---------------------------
__device__ __forceinline__ unsigned long long pack2_dup(float v) {
    unsigned long long r; uint32_t u = __float_as_uint(v);
    asm("mov.b64 %0, {%1,%2};" : "=l"(r) : "r"(u), "r"(u));
    return r;
}
__device__ __forceinline__ unsigned long long fma2(unsigned long long a,
                                                   unsigned long long b,
                                                   unsigned long long c) {
    unsigned long long d;
    asm("fma.rn.f32x2 %0, %1, %2, %3;" : "=l"(d) : "l"(a), "l"(b), "l"(c));
    return d;
}
__device__ __forceinline__ void unpack2(unsigned long long v, float& lo, float& hi) {
    uint32_t a, b;
    asm("mov.b64 {%0,%1}, %2;" : "=r"(a), "=r"(b) : "l"(v));
    lo = __uint_as_float(a); hi = __uint_as_float(b);
}

// ---------------- 1) transpose x (128, M) -> xt (M, 128) --------------------
__global__ void transpose_kernel(const float* __restrict__ x, float* __restrict__ xt) {
    __shared__ float tile[32][33];
    int mBase = blockIdx.x * 32, fBase = blockIdx.y * 32;
    int tx = threadIdx.x, ty = threadIdx.y;
#pragma unroll
    for (int i = 0; i < 32; i += 8)
        tile[ty + i][tx] = x[(size_t)(fBase + ty + i) * MM + mBase + tx];
    __syncthreads();
#pragma unroll
    for (int i = 0; i < 32; i += 8)
        xt[(size_t)(mBase + ty + i) * NF + fBase + tx] = tile[tx][ty + i];
}

// ---------------- CSR build --------------------------------------------------
__global__ void hist_kernel(const int* __restrict__ rows, int nnz,
                            int* __restrict__ cnt, int* __restrict__ pos) {
    int e = blockIdx.x * blockDim.x + threadIdx.x;
    if (e >= nnz) return;
    pos[e] = atomicAdd(&cnt[rows[e]], 1);
}

// block-level exclusive scan of 1024-elem chunks; emits block totals
__global__ void scanA_kernel(const int* __restrict__ cnt, int* __restrict__ rs,
                             int* __restrict__ bsum, int n) {
    __shared__ int wsum[32];
    int t = threadIdx.x;
    int i = blockIdx.x * 1024 + t;
    int v = (i < n) ? cnt[i] : 0;
    int lane = t & 31, wid = t >> 5;
    int incl = v;
#pragma unroll
    for (int d = 1; d < 32; d <<= 1) {
        int o = __shfl_up_sync(0xffffffffu, incl, d);
        if (lane >= d) incl += o;
    }
    if (lane == 31) wsum[wid] = incl;
    __syncthreads();
    if (wid == 0) {
        int w = (lane < 32) ? wsum[lane] : 0;
#pragma unroll
        for (int d = 1; d < 32; d <<= 1) {
            int o = __shfl_up_sync(0xffffffffu, w, d);
            if (lane >= d) w += o;
        }
        wsum[lane] = w;
    }
    __syncthreads();
    int base = (wid > 0) ? wsum[wid - 1] : 0;
    if (i < n) rs[i] = base + incl - v;            // exclusive
    if (t == 1023) bsum[blockIdx.x] = base + incl; // block total
}

__global__ void scanB_kernel(int* __restrict__ bsum, int nb) {
    if (threadIdx.x == 0 && blockIdx.x == 0) {
        int run = 0;
        for (int b = 0; b < nb; b++) { int t = bsum[b]; bsum[b] = run; run += t; }
    }
}

__global__ void scanC_kernel(int* __restrict__ rs, const int* __restrict__ bsum,
                             int n, int nnz) {
    int i = blockIdx.x * 1024 + threadIdx.x;
    if (i < n) rs[i] += bsum[blockIdx.x];
    if (i == 0) rs[n] = nnz;
}

__global__ void scatter_kernel(const int* __restrict__ rows, const int* __restrict__ cols,
                               const float* __restrict__ vals, const int* __restrict__ pos,
                               const int* __restrict__ rs, int2* __restrict__ ents, int nnz) {
    int e = blockIdx.x * blockDim.x + threadIdx.x;
    if (e >= nnz) return;
    int idx = rs[rows[e]] + pos[e];
    ents[idx] = make_int2(cols[e], __float_as_int(vals[e]));
}

// ---------------- 2) CSR SpMM: warp per row, one STG.128 per lane -----------
__global__ void spmm_csr_kernel(const int* __restrict__ rs, const int2* __restrict__ ents,
                                const float* __restrict__ in, float* __restrict__ out) {
    int r = (blockIdx.x * blockDim.x + threadIdx.x) >> 5;
    if (r >= MM) return;
    int lane = threadIdx.x & 31;
    int s = __ldg(rs + r), e = __ldg(rs + r + 1);
    float ax = 0.f, ay = 0.f, az = 0.f, aw = 0.f;
    for (int j = s; j < e; j++) {
        int2 ev = __ldg(ents + j);                 // warp-uniform, L1-sequential
        float v = __int_as_float(ev.y);
        float4 g = *reinterpret_cast<const float4*>(in + (size_t)ev.x * NF + lane * 4);
        ax += v * g.x; ay += v * g.y; az += v * g.z; aw += v * g.w;
    }
    float4 o = make_float4(ax, ay, az, aw);
    *reinterpret_cast<float4*>(out + (size_t)r * NF + lane * 4) = o;
}

// ---------------- 3) fold theta -> Wt[j][o] ---------------------------------
__global__ void wprep_kernel(const float* __restrict__ theta, float* __restrict__ w) {
    int i = blockIdx.x * blockDim.x + threadIdx.x;   // i = (k*64+c)*64 + o
    if (i >= KTOT * 64 * 64) return;
    int o = i & 63;
    int c = (i >> 6) & 63;
    int k = i >> 12;
    const int kmap[KTOT] = {0, 1, 2, 4, 5};
    float v = theta[(o * 64 + c) * 6 + kmap[k]];
    if (k == 0) v += theta[(o * 64 + c) * 6 + 3];
    w[i] = v;
}

// ---------------- 4) combine: y[b,o,m] = sum_j Wt[j][o] * U[j][(b,m)] -------
// Block: 256 threads = 2 o-halves x 128 thread-slots; each thread owns 2 m
// and 32 outputs -> 32 packed u64 accumulators. W loads: 128B per jc per
// thread serving 64 fma2 (2B/fma2, 4x less LDS than round 1).
#define CMB_SMEM_FLOATS (KTOT * 64 * 64 + 256 * 65)
#define CMB_SMEM_BYTES  (CMB_SMEM_FLOATS * 4)

__global__ __launch_bounds__(256, 1)
void combine_kernel(const float* __restrict__ bias, float* __restrict__ y) {
    extern __shared__ float smem[];
    float* ws = smem;                       // [320][64]
    float* us = smem + KTOT * 64 * 64;      // [256][65]

    int t  = threadIdx.x;
    int th = t & 127;                       // m slot within tile
    int oh = t >> 7;                        // output half: o in [oh*32, oh*32+32)
    int b  = blockIdx.y;
    int mBase = blockIdx.x * 256;
    int m0 = mBase + th, m1 = m0 + 128;

    for (int i = t; i < KTOT * 64 * 64; i += 256) ws[i] = g_w[i];

    unsigned long long acc0[16], acc1[16];
#pragma unroll
    for (int p = 0; p < 16; p++) { acc0[p] = 0ull; acc1[p] = 0ull; }

    const float* bufs[KTOT] = {g_xt, g_p1l, g_p2l, g_p1u, g_p2u};

    for (int k = 0; k < KTOT; k++) {
        __syncthreads();                    // protect previous us tile
        const float* src = bufs[k];
        for (int i = t; i < 256 * 64; i += 256) {
            int ml = i >> 6, c = i & 63;
            int mm = mBase + ml;
            us[ml * 65 + c] = (mm < MM) ? src[(size_t)mm * NF + b * 64 + c] : 0.0f;
        }
        __syncthreads();
        const float* wk = ws + k * 64 * 64 + oh * 32;
#pragma unroll 4
        for (int jc = 0; jc < 64; jc++) {
            unsigned long long u0 = pack2_dup(us[th * 65 + jc]);
            unsigned long long u1 = pack2_dup(us[(th + 128) * 65 + jc]);
            const ulonglong2* wv =
                reinterpret_cast<const ulonglong2*>(wk + jc * 64);
#pragma unroll
            for (int q = 0; q < 8; q++) {
                ulonglong2 wq = wv[q];      // (w[o0],w[o0+1]),(w[o0+2],w[o0+3])
                acc0[2 * q]     = fma2(wq.x, u0, acc0[2 * q]);
                acc0[2 * q + 1] = fma2(wq.y, u0, acc0[2 * q + 1]);
                acc1[2 * q]     = fma2(wq.x, u1, acc1[2 * q]);
                acc1[2 * q + 1] = fma2(wq.y, u1, acc1[2 * q + 1]);
            }
        }
    }

#pragma unroll
    for (int q = 0; q < 8; q++) {
        int o = oh * 32 + 4 * q;
        float b0 = bias[o], b1 = bias[o + 1], b2 = bias[o + 2], b3 = bias[o + 3];
        float v0, v1, v2, v3;
        if (m0 < MM) {
            unpack2(acc0[2 * q], v0, v1);
            unpack2(acc0[2 * q + 1], v2, v3);
            y[((size_t)b * 64 + o    ) * MM + m0] = v0 + b0;
            y[((size_t)b * 64 + o + 1) * MM + m0] = v1 + b1;
            y[((size_t)b * 64 + o + 2) * MM + m0] = v2 + b2;
            y[((size_t)b * 64 + o + 3) * MM + m0] = v3 + b3;
        }
        if (m1 < MM) {
            unpack2(acc1[2 * q], v0, v1);
            unpack2(acc1[2 * q + 1], v2, v3);
            y[((size_t)b * 64 + o    ) * MM + m1] = v0 + b0;
            y[((size_t)b * 64 + o + 1) * MM + m1] = v1 + b1;
            y[((size_t)b * 64 + o + 2) * MM + m1] = v2 + b2;
            y[((size_t)b * 64 + o + 3) * MM + m1] = v3 + b3;
        }
    }
}

// ---------------- launch ----------------------------------------------------
extern "C" void kernel_launch(void* const* d_in, const int* in_sizes, int n_in,
                              void* d_out, int out_size) {
    const int*   LlI  = (const int*)  d_in[0];   // (2, NNZ): rows then cols
    const float* LlV  = (const float*)d_in[1];
    const int*   LuI  = (const int*)  d_in[2];
    const float* LuV  = (const float*)d_in[3];
    const float* x    = (const float*)d_in[4];
    const float* th   = (const float*)d_in[5];
    const float* bias = (const float*)d_in[6];
    float*       y    = (float*)d_out;
    int nnz = in_sizes[1];                       // Ll_values element count

    float *xt, *p1l, *p2l, *p1u, *p2u, *w;
    cudaGetSymbolAddress((void**)&xt,  g_xt);
    cudaGetSymbolAddress((void**)&p1l, g_p1l);
    cudaGetSymbolAddress((void**)&p2l, g_p2l);
    cudaGetSymbolAddress((void**)&p1u, g_p1u);
    cudaGetSymbolAddress((void**)&p2u, g_p2u);
    cudaGetSymbolAddress((void**)&w,   g_w);

    int  *cnt, *rsb, *bsum, *pos;
    int2 *ents;
    cudaGetSymbolAddress((void**)&cnt,  g_cnt);
    cudaGetSymbolAddress((void**)&rsb,  g_rs);
    cudaGetSymbolAddress((void**)&bsum, g_bsum);
    cudaGetSymbolAddress((void**)&pos,  g_pos);
    cudaGetSymbolAddress((void**)&ents, g_ents);

    const int* rowsA[2] = {LlI, LuI};
    const int* colsA[2] = {LlI + nnz, LuI + nnz};
    const float* valsA[2] = {LlV, LuV};

    cudaMemsetAsync(cnt, 0, 2 * MM * sizeof(int));

    int eb = (nnz + 255) / 256;
    int nScanBlk = (MM + 1023) / 1024;           // 98
    for (int s = 0; s < 2; s++) {
        int*  cs = cnt  + s * MM;
        int*  rs = rsb  + s * (MM + 1);
        int*  bs = bsum + s * 128;
        int*  ps = pos  + s * NNZCAP;
        int2* es = ents + s * NNZCAP;
        hist_kernel<<<eb, 256>>>(rowsA[s], nnz, cs, ps);
        scanA_kernel<<<nScanBlk, 1024>>>(cs, rs, bs, MM);
        scanB_kernel<<<1, 32>>>(bs, nScanBlk);
        scanC_kernel<<<nScanBlk, 1024>>>(rs, bs, MM, nnz);
        scatter_kernel<<<eb, 256>>>(rowsA[s], colsA[s], valsA[s], ps, rs, es, nnz);
    }

    transpose_kernel<<<dim3(MM / 32, NF / 32), dim3(32, 8)>>>(x, xt);
    wprep_kernel<<<(KTOT * 64 * 64 + 255) / 256, 256>>>(th, w);

    int spmmBlocks = (MM * 32 + 255) / 256;
    int*  rsL = rsb;            int2* entsL = ents;
    int*  rsU = rsb + (MM + 1); int2* entsU = ents + NNZCAP;
    spmm_csr_kernel<<<spmmBlocks, 256>>>(rsL, entsL, xt,  p1l);
    spmm_csr_kernel<<<spmmBlocks, 256>>>(rsL, entsL, p1l, p2l);
    spmm_csr_kernel<<<spmmBlocks, 256>>>(rsU, entsU, xt,  p1u);
    spmm_csr_kernel<<<spmmBlocks, 256>>>(rsU, entsU, p1u, p2u);

    cudaFuncSetAttribute(combine_kernel,
                         cudaFuncAttributeMaxDynamicSharedMemorySize, CMB_SMEM_BYTES);
    combine_kernel<<<dim3((MM + 255) / 256, 2), 256, CMB_SMEM_BYTES>>>(bias, y);
}

// round 3
// speedup vs baseline: 1.3947x; 1.0009x over previous
#include <cuda_runtime.h>
#include <cstdint>

#define MM    100000   // simplices
#define NF    128      // B * C_IN features per simplex
#define KTOT  5        // [x, Ll x, Ll^2 x, Lu x, Lu^2 x]
#define NNZCAP 800000

// ---------------- scratch (device globals: no allocations allowed) ----------
__device__ float g_xt [(size_t)MM * NF];
__device__ float g_p1l[(size_t)MM * NF];
__device__ float g_p2l[(size_t)MM * NF];
__device__ float g_p1u[(size_t)MM * NF];
__device__ float g_p2u[(size_t)MM * NF];
__device__ float g_w  [KTOT * 64 * 64];        // Wt[j][o], j = k*64 + c

// CSR build scratch (2 matrices)
__device__ int  g_cnt [2 * MM];                // hist counts, then running offsets
__device__ int  g_rs  [2 * (MM + 1)];
__device__ int  g_bsum[2 * 128];
__device__ int2 g_ents[2 * NNZCAP];            // {col, val_bits} grouped by row

// ---------------- packed fp32x2 helpers (sm_100+) ---------------------------
__device__ __forceinline__ unsigned long long pack2_dup(float v) {
    unsigned long long r; uint32_t u = __float_as_uint(v);
    asm("mov.b64 %0, {%1,%2};" : "=l"(r) : "r"(u), "r"(u));
    return r;
}
__device__ __forceinline__ unsigned long long fma2(unsigned long long a,
                                                   unsigned long long b,
                                                   unsigned long long c) {
    unsigned long long d;
    asm("fma.rn.f32x2 %0, %1, %2, %3;" : "=l"(d) : "l"(a), "l"(b), "l"(c));
    return d;
}
__device__ __forceinline__ void unpack2(unsigned long long v, float& lo, float& hi) {
    uint32_t a, b;
    asm("mov.b64 {%0,%1}, %2;" : "=r"(a), "=r"(b) : "l"(v));
    lo = __uint_as_float(a); hi = __uint_as_float(b);
}

// ---------------- 1) transpose x (128, M) -> xt (M, 128) --------------------
__global__ void transpose_kernel(const float* __restrict__ x, float* __restrict__ xt) {
    __shared__ float tile[32][33];
    int mBase = blockIdx.x * 32, fBase = blockIdx.y * 32;
    int tx = threadIdx.x, ty = threadIdx.y;
#pragma unroll
    for (int i = 0; i < 32; i += 8)
        tile[ty + i][tx] = x[(size_t)(fBase + ty + i) * MM + mBase + tx];
    __syncthreads();
#pragma unroll
    for (int i = 0; i < 32; i += 8)
        xt[(size_t)(mBase + ty + i) * NF + fBase + tx] = tile[tx][ty + i];
}

// ---------------- CSR build (both matrices per launch) -----------------------
__global__ void hist_dual_kernel(const int* __restrict__ rowsL,
                                 const int* __restrict__ rowsU,
                                 int nnz, int* __restrict__ cnt) {
    int e = blockIdx.x * blockDim.x + threadIdx.x;
    if (e >= 2 * nnz) return;
    int s = (e >= nnz);
    int r = s ? rowsU[e - nnz] : rowsL[e];
    atomicAdd(&cnt[s * MM + r], 1);
}

// block-level exclusive scan of 1024-elem chunks; emits block totals
__global__ void scanA_kernel(const int* __restrict__ cntB, int* __restrict__ rsB,
                             int* __restrict__ bsumB, int n) {
    __shared__ int wsum[32];
    const int* cnt = cntB + blockIdx.y * MM;
    int* rs   = rsB   + blockIdx.y * (MM + 1);
    int* bsum = bsumB + blockIdx.y * 128;
    int t = threadIdx.x;
    int i = blockIdx.x * 1024 + t;
    int v = (i < n) ? cnt[i] : 0;
    int lane = t & 31, wid = t >> 5;
    int incl = v;
#pragma unroll
    for (int d = 1; d < 32; d <<= 1) {
        int o = __shfl_up_sync(0xffffffffu, incl, d);
        if (lane >= d) incl += o;
    }
    if (lane == 31) wsum[wid] = incl;
    __syncthreads();
    if (wid == 0) {
        int w = wsum[lane];
#pragma unroll
        for (int d = 1; d < 32; d <<= 1) {
            int o = __shfl_up_sync(0xffffffffu, w, d);
            if (lane >= d) w += o;
        }
        wsum[lane] = w;
    }
    __syncthreads();
    int base = (wid > 0) ? wsum[wid - 1] : 0;
    if (i < n) rs[i] = base + incl - v;            // exclusive
    if (t == 1023) bsum[blockIdx.x] = base + incl; // block total
}

__global__ void scanB_kernel(int* __restrict__ bsumB, int nb) {
    if (threadIdx.x == 0) {
        int* bsum = bsumB + blockIdx.x * 128;
        int run = 0;
        for (int b = 0; b < nb; b++) { int t = bsum[b]; bsum[b] = run; run += t; }
    }
}

// adds block offsets; also seeds cnt[] with the exclusive offsets so scatter
// can claim slots with atomicAdd (no separate pos array)
__global__ void scanC_kernel(int* __restrict__ rsB, int* __restrict__ cntB,
                             const int* __restrict__ bsumB, int n, int nnz) {
    int s = blockIdx.y;
    int* rs = rsB + s * (MM + 1);
    int* cnt = cntB + s * MM;
    int i = blockIdx.x * 1024 + threadIdx.x;
    if (i < n) {
        int v = rs[i] + bsumB[s * 128 + blockIdx.x];
        rs[i] = v;
        cnt[i] = v;
    }
    if (i == 0) rs[n] = nnz;
}

__global__ void scatter_dual_kernel(const int* __restrict__ LlI, const int* __restrict__ LuI,
                                    const float* __restrict__ LlV, const float* __restrict__ LuV,
                                    int* __restrict__ cnt, int2* __restrict__ ents, int nnz) {
    int e = blockIdx.x * blockDim.x + threadIdx.x;
    if (e >= 2 * nnz) return;
    int s = (e >= nnz);
    int el = e - s * nnz;
    int r   = s ? LuI[el]       : LlI[el];
    int c   = s ? LuI[el + nnz] : LlI[el + nnz];
    float v = s ? LuV[el]       : LlV[el];
    int idx = atomicAdd(&cnt[s * MM + r], 1);
    ents[(size_t)s * NNZCAP + idx] = make_int2(c, __float_as_int(v));
}

// ---------------- 2) dual CSR SpMM: warp per row, MLP-4 inner loop ----------
__global__ void spmm_dual_kernel(const int* __restrict__ rsB, const int2* __restrict__ entsB,
                                 const float* __restrict__ in0, const float* __restrict__ in1,
                                 float* __restrict__ out0, float* __restrict__ out1) {
    int w = (blockIdx.x * blockDim.x + threadIdx.x) >> 5;
    if (w >= 2 * MM) return;
    int s = (w >= MM);
    int r = w - s * MM;
    int lane = threadIdx.x & 31;
    const int*  rs   = rsB + s * (MM + 1);
    const int2* ents = entsB + (size_t)s * NNZCAP;
    const float* in  = s ? in1 : in0;
    float*       out = s ? out1 : out0;

    int j = __ldg(rs + r);
    int n = __ldg(rs + r + 1) - j;
    float ax = 0.f, ay = 0.f, az = 0.f, aw = 0.f;

    for (; n >= 4; n -= 4, j += 4) {
        int2 e0 = __ldg(ents + j);
        int2 e1 = __ldg(ents + j + 1);
        int2 e2 = __ldg(ents + j + 2);
        int2 e3 = __ldg(ents + j + 3);
        float4 g0 = __ldg(reinterpret_cast<const float4*>(in + (size_t)e0.x * NF) + lane);
        float4 g1 = __ldg(reinterpret_cast<const float4*>(in + (size_t)e1.x * NF) + lane);
        float4 g2 = __ldg(reinterpret_cast<const float4*>(in + (size_t)e2.x * NF) + lane);
        float4 g3 = __ldg(reinterpret_cast<const float4*>(in + (size_t)e3.x * NF) + lane);
        float v0 = __int_as_float(e0.y), v1 = __int_as_float(e1.y);
        float v2 = __int_as_float(e2.y), v3 = __int_as_float(e3.y);
        ax += v0 * g0.x; ay += v0 * g0.y; az += v0 * g0.z; aw += v0 * g0.w;
        ax += v1 * g1.x; ay += v1 * g1.y; az += v1 * g1.z; aw += v1 * g1.w;
        ax += v2 * g2.x; ay += v2 * g2.y; az += v2 * g2.z; aw += v2 * g2.w;
        ax += v3 * g3.x; ay += v3 * g3.y; az += v3 * g3.z; aw += v3 * g3.w;
    }
    for (; n > 0; n--, j++) {
        int2 ev = __ldg(ents + j);
        float v = __int_as_float(ev.y);
        float4 g = __ldg(reinterpret_cast<const float4*>(in + (size_t)ev.x * NF) + lane);
        ax += v * g.x; ay += v * g.y; az += v * g.z; aw += v * g.w;
    }
    float4 o = make_float4(ax, ay, az, aw);
    *reinterpret_cast<float4*>(out + (size_t)r * NF + lane * 4) = o;
}

// ---------------- 3) fold theta -> Wt[j][o] ---------------------------------
__global__ void wprep_kernel(const float* __restrict__ theta, float* __restrict__ w) {
    int i = blockIdx.x * blockDim.x + threadIdx.x;   // i = (k*64+c)*64 + o
    if (i >= KTOT * 64 * 64) return;
    int o = i & 63;
    int c = (i >> 6) & 63;
    int k = i >> 12;
    const int kmap[KTOT] = {0, 1, 2, 4, 5};
    float v = theta[(o * 64 + c) * 6 + kmap[k]];
    if (k == 0) v += theta[(o * 64 + c) * 6 + 3];
    w[i] = v;
}

// ---------------- 4) combine: y[b,o,m] = sum_j Wt[j][o] * U[j][(b,m)] -------
// Block: 256 threads = 2 o-halves x 128 thread-slots; each thread owns 2 m
// and 32 outputs -> 32 packed u64 accumulators.
#define CMB_SMEM_FLOATS (KTOT * 64 * 64 + 256 * 65)
#define CMB_SMEM_BYTES  (CMB_SMEM_FLOATS * 4)

__global__ __launch_bounds__(256, 1)
void combine_kernel(const float* __restrict__ bias, float* __restrict__ y) {
    extern __shared__ float smem[];
    float* ws = smem;                       // [320][64]
    float* us = smem + KTOT * 64 * 64;      // [256][65]

    int t  = threadIdx.x;
    int th = t & 127;                       // m slot within tile
    int oh = t >> 7;                        // output half: o in [oh*32, oh*32+32)
    int b  = blockIdx.y;
    int mBase = blockIdx.x * 256;
    int m0 = mBase + th, m1 = m0 + 128;

    for (int i = t; i < KTOT * 64 * 64; i += 256) ws[i] = g_w[i];

    unsigned long long acc0[16], acc1[16];
#pragma unroll
    for (int p = 0; p < 16; p++) { acc0[p] = 0ull; acc1[p] = 0ull; }

    const float* bufs[KTOT] = {g_xt, g_p1l, g_p2l, g_p1u, g_p2u};

    for (int k = 0; k < KTOT; k++) {
        __syncthreads();                    // protect previous us tile
        const float* src = bufs[k];
        for (int i = t; i < 256 * 64; i += 256) {
            int ml = i >> 6, c = i & 63;
            int mm = mBase + ml;
            us[ml * 65 + c] = (mm < MM) ? src[(size_t)mm * NF + b * 64 + c] : 0.0f;
        }
        __syncthreads();
        const float* wk = ws + k * 64 * 64 + oh * 32;
#pragma unroll 4
        for (int jc = 0; jc < 64; jc++) {
            unsigned long long u0 = pack2_dup(us[th * 65 + jc]);
            unsigned long long u1 = pack2_dup(us[(th + 128) * 65 + jc]);
            const ulonglong2* wv =
                reinterpret_cast<const ulonglong2*>(wk + jc * 64);
#pragma unroll
            for (int q = 0; q < 8; q++) {
                ulonglong2 wq = wv[q];      // (w[o0],w[o0+1]),(w[o0+2],w[o0+3])
                acc0[2 * q]     = fma2(wq.x, u0, acc0[2 * q]);
                acc0[2 * q + 1] = fma2(wq.y, u0, acc0[2 * q + 1]);
                acc1[2 * q]     = fma2(wq.x, u1, acc1[2 * q]);
                acc1[2 * q + 1] = fma2(wq.y, u1, acc1[2 * q + 1]);
            }
        }
    }

#pragma unroll
    for (int q = 0; q < 8; q++) {
        int o = oh * 32 + 4 * q;
        float b0 = bias[o], b1 = bias[o + 1], b2 = bias[o + 2], b3 = bias[o + 3];
        float v0, v1, v2, v3;
        if (m0 < MM) {
            unpack2(acc0[2 * q], v0, v1);
            unpack2(acc0[2 * q + 1], v2, v3);
            y[((size_t)b * 64 + o    ) * MM + m0] = v0 + b0;
            y[((size_t)b * 64 + o + 1) * MM + m0] = v1 + b1;
            y[((size_t)b * 64 + o + 2) * MM + m0] = v2 + b2;
            y[((size_t)b * 64 + o + 3) * MM + m0] = v3 + b3;
        }
        if (m1 < MM) {
            unpack2(acc1[2 * q], v0, v1);
            unpack2(acc1[2 * q + 1], v2, v3);
            y[((size_t)b * 64 + o    ) * MM + m1] = v0 + b0;
            y[((size_t)b * 64 + o + 1) * MM + m1] = v1 + b1;
            y[((size_t)b * 64 + o + 2) * MM + m1] = v2 + b2;
            y[((size_t)b * 64 + o + 3) * MM + m1] = v3 + b3;
        }
    }
}

// ---------------- launch ----------------------------------------------------
extern "C" void kernel_launch(void* const* d_in, const int* in_sizes, int n_in,
                              void* d_out, int out_size) {
    const int*   LlI  = (const int*)  d_in[0];   // (2, NNZ): rows then cols
    const float* LlV  = (const float*)d_in[1];
    const int*   LuI  = (const int*)  d_in[2];
    const float* LuV  = (const float*)d_in[3];
    const float* x    = (const float*)d_in[4];
    const float* th   = (const float*)d_in[5];
    const float* bias = (const float*)d_in[6];
    float*       y    = (float*)d_out;
    int nnz = in_sizes[1];                       // Ll_values element count

    float *xt, *p1l, *p2l, *p1u, *p2u, *w;
    cudaGetSymbolAddress((void**)&xt,  g_xt);
    cudaGetSymbolAddress((void**)&p1l, g_p1l);
    cudaGetSymbolAddress((void**)&p2l, g_p2l);
    cudaGetSymbolAddress((void**)&p1u, g_p1u);
    cudaGetSymbolAddress((void**)&p2u, g_p2u);
    cudaGetSymbolAddress((void**)&w,   g_w);

    int  *cnt, *rsb, *bsum;
    int2 *ents;
    cudaGetSymbolAddress((void**)&cnt,  g_cnt);
    cudaGetSymbolAddress((void**)&rsb,  g_rs);
    cudaGetSymbolAddress((void**)&bsum, g_bsum);
    cudaGetSymbolAddress((void**)&ents, g_ents);

    cudaMemsetAsync(cnt, 0, 2 * MM * sizeof(int));

    int eb2 = (2 * nnz + 255) / 256;
    int nScanBlk = (MM + 1023) / 1024;           // 98
    hist_dual_kernel<<<eb2, 256>>>(LlI, LuI, nnz, cnt);
    scanA_kernel<<<dim3(nScanBlk, 2), 1024>>>(cnt, rsb, bsum, MM);
    scanB_kernel<<<2, 32>>>(bsum, nScanBlk);
    scanC_kernel<<<dim3(nScanBlk, 2), 1024>>>(rsb, cnt, bsum, MM, nnz);
    scatter_dual_kernel<<<eb2, 256>>>(LlI, LuI, LlV, LuV, cnt, ents, nnz);

    transpose_kernel<<<dim3(MM / 32, NF / 32), dim3(32, 8)>>>(x, xt);
    wprep_kernel<<<(KTOT * 64 * 64 + 255) / 256, 256>>>(th, w);

    int spmmBlocks = (2 * MM * 32 + 255) / 256;
    spmm_dual_kernel<<<spmmBlocks, 256>>>(rsb, ents, xt,  xt,  p1l, p1u);   // pass A
    spmm_dual_kernel<<<spmmBlocks, 256>>>(rsb, ents, p1l, p1u, p2l, p2u);   // pass B

    cudaFuncSetAttribute(combine_kernel,
                         cudaFuncAttributeMaxDynamicSharedMemorySize, CMB_SMEM_BYTES);
    combine_kernel<<<dim3((MM + 255) / 256, 2), 256, CMB_SMEM_BYTES>>>(bias, y);
}

// round 4
// speedup vs baseline: 1.8544x; 1.3296x over previous
#include <cuda_runtime.h>
#include <cstdint>

#define MM    100000   // simplices
#define NF    128      // B * C_IN features per simplex
#define KTOT  5        // [x, Ll x, Ll^2 x, Lu x, Lu^2 x]
#define NNZCAP 800000

// ---------------- scratch (device globals: no allocations allowed) ----------
__device__ float g_xt [(size_t)MM * NF];
__device__ float g_p1l[(size_t)MM * NF];
__device__ float g_p2l[(size_t)MM * NF];
__device__ float g_p1u[(size_t)MM * NF];
__device__ float g_p2u[(size_t)MM * NF];
__device__ float g_w  [KTOT * 64 * 64];        // Wt[j][o], j = k*64 + c

// CSR build scratch (2 matrices)
__device__ int  g_cnt [2 * MM];                // hist counts, then running offsets
__device__ int  g_rs  [2 * (MM + 1)];
__device__ int  g_bsum[2 * 128];
__device__ int2 g_ents[2 * NNZCAP];            // {col, val_bits} grouped by row

// ---------------- packed fp32x2 helpers (sm_100+) ---------------------------
__device__ __forceinline__ unsigned long long pack2_dup(float v) {
    unsigned long long r; uint32_t u = __float_as_uint(v);
    asm("mov.b64 %0, {%1,%2};" : "=l"(r) : "r"(u), "r"(u));
    return r;
}
__device__ __forceinline__ unsigned long long fma2(unsigned long long a,
                                                   unsigned long long b,
                                                   unsigned long long c) {
    unsigned long long d;
    asm("fma.rn.f32x2 %0, %1, %2, %3;" : "=l"(d) : "l"(a), "l"(b), "l"(c));
    return d;
}
__device__ __forceinline__ void unpack2(unsigned long long v, float& lo, float& hi) {
    uint32_t a, b;
    asm("mov.b64 {%0,%1}, %2;" : "=r"(a), "=r"(b) : "l"(v));
    lo = __uint_as_float(a); hi = __uint_as_float(b);
}

// ---------------- 1) transpose x (128, M) -> xt (M, 128) --------------------
__global__ void transpose_kernel(const float* __restrict__ x, float* __restrict__ xt) {
    __shared__ float tile[32][33];
    int mBase = blockIdx.x * 32, fBase = blockIdx.y * 32;
    int tx = threadIdx.x, ty = threadIdx.y;
#pragma unroll
    for (int i = 0; i < 32; i += 8)
        tile[ty + i][tx] = x[(size_t)(fBase + ty + i) * MM + mBase + tx];
    __syncthreads();
#pragma unroll
    for (int i = 0; i < 32; i += 8)
        xt[(size_t)(mBase + ty + i) * NF + fBase + tx] = tile[tx][ty + i];
}

// ---------------- CSR build (both matrices per launch) -----------------------
__global__ void hist_dual_kernel(const int* __restrict__ rowsL,
                                 const int* __restrict__ rowsU,
                                 int nnz, int* __restrict__ cnt) {
    int e = blockIdx.x * blockDim.x + threadIdx.x;
    if (e >= 2 * nnz) return;
    int s = (e >= nnz);
    int r = s ? rowsU[e - nnz] : rowsL[e];
    atomicAdd(&cnt[s * MM + r], 1);
}

// block-level exclusive scan of 1024-elem chunks; emits block totals
__global__ void scanA_kernel(const int* __restrict__ cntB, int* __restrict__ rsB,
                             int* __restrict__ bsumB, int n) {
    __shared__ int wsum[32];
    const int* cnt = cntB + blockIdx.y * MM;
    int* rs   = rsB   + blockIdx.y * (MM + 1);
    int* bsum = bsumB + blockIdx.y * 128;
    int t = threadIdx.x;
    int i = blockIdx.x * 1024 + t;
    int v = (i < n) ? cnt[i] : 0;
    int lane = t & 31, wid = t >> 5;
    int incl = v;
#pragma unroll
    for (int d = 1; d < 32; d <<= 1) {
        int o = __shfl_up_sync(0xffffffffu, incl, d);
        if (lane >= d) incl += o;
    }
    if (lane == 31) wsum[wid] = incl;
    __syncthreads();
    if (wid == 0) {
        int w = wsum[lane];
#pragma unroll
        for (int d = 1; d < 32; d <<= 1) {
            int o = __shfl_up_sync(0xffffffffu, w, d);
            if (lane >= d) w += o;
        }
        wsum[lane] = w;
    }
    __syncthreads();
    int base = (wid > 0) ? wsum[wid - 1] : 0;
    if (i < n) rs[i] = base + incl - v;            // exclusive
    if (t == 1023) bsum[blockIdx.x] = base + incl; // block total
}

// parallel one-block exclusive scan of the <=128 block totals (per matrix)
__global__ void scanB_kernel(int* __restrict__ bsumB, int nb) {
    __shared__ int wtot[4];
    int s = blockIdx.x;
    int* bsum = bsumB + s * 128;
    int t = threadIdx.x;                 // 128 threads
    int lane = t & 31, wid = t >> 5;
    int v = (t < nb) ? bsum[t] : 0;
    int incl = v;
#pragma unroll
    for (int d = 1; d < 32; d <<= 1) {
        int o = __shfl_up_sync(0xffffffffu, incl, d);
        if (lane >= d) incl += o;
    }
    if (lane == 31) wtot[wid] = incl;
    __syncthreads();
    if (t == 0) {
        int run = 0;
#pragma unroll
        for (int i = 0; i < 4; i++) { int x = wtot[i]; wtot[i] = run; run += x; }
    }
    __syncthreads();
    if (t < nb) bsum[t] = wtot[wid] + incl - v;
}

// adds block offsets; also seeds cnt[] with the exclusive offsets so scatter
// can claim slots with atomicAdd (no separate pos array)
__global__ void scanC_kernel(int* __restrict__ rsB, int* __restrict__ cntB,
                             const int* __restrict__ bsumB, int n, int nnz) {
    int s = blockIdx.y;
    int* rs = rsB + s * (MM + 1);
    int* cnt = cntB + s * MM;
    int i = blockIdx.x * 1024 + threadIdx.x;
    if (i < n) {
        int v = rs[i] + bsumB[s * 128 + blockIdx.x];
        rs[i] = v;
        cnt[i] = v;
    }
    if (i == 0) rs[n] = nnz;
}

__global__ void scatter_dual_kernel(const int* __restrict__ LlI, const int* __restrict__ LuI,
                                    const float* __restrict__ LlV, const float* __restrict__ LuV,
                                    int* __restrict__ cnt, int2* __restrict__ ents, int nnz) {
    int e = blockIdx.x * blockDim.x + threadIdx.x;
    if (e >= 2 * nnz) return;
    int s = (e >= nnz);
    int el = e - s * nnz;
    int r   = s ? LuI[el]       : LlI[el];
    int c   = s ? LuI[el + nnz] : LlI[el + nnz];
    float v = s ? LuV[el]       : LlV[el];
    int idx = atomicAdd(&cnt[s * MM + r], 1);
    ents[(size_t)s * NNZCAP + idx] = make_int2(c, __float_as_int(v));
}

// ---------------- 2) dual CSR SpMM: warp per row, MLP-4 inner loop ----------
__global__ void spmm_dual_kernel(const int* __restrict__ rsB, const int2* __restrict__ entsB,
                                 const float* __restrict__ in0, const float* __restrict__ in1,
                                 float* __restrict__ out0, float* __restrict__ out1) {
    int w = (blockIdx.x * blockDim.x + threadIdx.x) >> 5;
    if (w >= 2 * MM) return;
    int s = (w >= MM);
    int r = w - s * MM;
    int lane = threadIdx.x & 31;
    const int*  rs   = rsB + s * (MM + 1);
    const int2* ents = entsB + (size_t)s * NNZCAP;
    const float* in  = s ? in1 : in0;
    float*       out = s ? out1 : out0;

    int j = __ldg(rs + r);
    int n = __ldg(rs + r + 1) - j;
    float ax = 0.f, ay = 0.f, az = 0.f, aw = 0.f;

    for (; n >= 4; n -= 4, j += 4) {
        int2 e0 = __ldg(ents + j);
        int2 e1 = __ldg(ents + j + 1);
        int2 e2 = __ldg(ents + j + 2);
        int2 e3 = __ldg(ents + j + 3);
        float4 g0 = __ldg(reinterpret_cast<const float4*>(in + (size_t)e0.x * NF) + lane);
        float4 g1 = __ldg(reinterpret_cast<const float4*>(in + (size_t)e1.x * NF) + lane);
        float4 g2 = __ldg(reinterpret_cast<const float4*>(in + (size_t)e2.x * NF) + lane);
        float4 g3 = __ldg(reinterpret_cast<const float4*>(in + (size_t)e3.x * NF) + lane);
        float v0 = __int_as_float(e0.y), v1 = __int_as_float(e1.y);
        float v2 = __int_as_float(e2.y), v3 = __int_as_float(e3.y);
        ax += v0 * g0.x; ay += v0 * g0.y; az += v0 * g0.z; aw += v0 * g0.w;
        ax += v1 * g1.x; ay += v1 * g1.y; az += v1 * g1.z; aw += v1 * g1.w;
        ax += v2 * g2.x; ay += v2 * g2.y; az += v2 * g2.z; aw += v2 * g2.w;
        ax += v3 * g3.x; ay += v3 * g3.y; az += v3 * g3.z; aw += v3 * g3.w;
    }
    for (; n > 0; n--, j++) {
        int2 ev = __ldg(ents + j);
        float v = __int_as_float(ev.y);
        float4 g = __ldg(reinterpret_cast<const float4*>(in + (size_t)ev.x * NF) + lane);
        ax += v * g.x; ay += v * g.y; az += v * g.z; aw += v * g.w;
    }
    float4 o = make_float4(ax, ay, az, aw);
    *reinterpret_cast<float4*>(out + (size_t)r * NF + lane * 4) = o;
}

// ---------------- 3) fold theta -> Wt[j][o] ---------------------------------
__global__ void wprep_kernel(const float* __restrict__ theta, float* __restrict__ w) {
    int i = blockIdx.x * blockDim.x + threadIdx.x;   // i = (k*64+c)*64 + o
    if (i >= KTOT * 64 * 64) return;
    int o = i & 63;
    int c = (i >> 6) & 63;
    int k = i >> 12;
    const int kmap[KTOT] = {0, 1, 2, 4, 5};
    float v = theta[(o * 64 + c) * 6 + kmap[k]];
    if (k == 0) v += theta[(o * 64 + c) * 6 + 3];
    w[i] = v;
}

// ---------------- 4) combine v2: 512 threads, 512-m tile, per-k W staging ---
// Block: 512 threads = 2 o-halves x 256 m slots; each thread owns 2 m values
// (m0 = base+th, m1 = m0+256) and 32 outputs -> 32 packed u64 accumulators.
// 4 warps/SMSP (vs 2 before) to cover staging latency and saturate fma2 issue.
#define CMB_THREADS 512
#define CMB_TILE    512
#define CMB_SMEM_FLOATS (64 * 64 + CMB_TILE * 65)
#define CMB_SMEM_BYTES  (CMB_SMEM_FLOATS * 4)

__global__ __launch_bounds__(CMB_THREADS, 1)
void combine_kernel(const float* __restrict__ bias, float* __restrict__ y) {
    extern __shared__ float smem[];
    float* ws = smem;                       // [64][64]   current k slice
    float* us = smem + 64 * 64;             // [512][65]

    int t  = threadIdx.x;
    int th = t & 255;                       // m slot within tile
    int oh = t >> 8;                        // output half: o in [oh*32, oh*32+32)
    int b  = blockIdx.y;
    int mBase = blockIdx.x * CMB_TILE;
    int m0 = mBase + th, m1 = m0 + 256;

    unsigned long long acc0[16], acc1[16];
#pragma unroll
    for (int p = 0; p < 16; p++) { acc0[p] = 0ull; acc1[p] = 0ull; }

    const float* bufs[KTOT] = {g_xt, g_p1l, g_p2l, g_p1u, g_p2u};

    for (int k = 0; k < KTOT; k++) {
        __syncthreads();                    // previous tile fully consumed
        // stage this k's W slice: 4096 floats via float4
        const float4* wsrc = reinterpret_cast<const float4*>(g_w + k * 64 * 64);
        reinterpret_cast<float4*>(ws)[t]       = wsrc[t];
        reinterpret_cast<float4*>(ws)[t + 512] = wsrc[t + 512];
        // stage 512 m-rows x 64 channels, float4 loads (coalesced 256B runs)
        const float* src = bufs[k];
#pragma unroll
        for (int i = t; i < CMB_TILE * 16; i += CMB_THREADS) {
            int ml = i >> 4, c4 = (i & 15) << 2;
            int mm = mBase + ml;
            float4 v = (mm < MM)
                ? *reinterpret_cast<const float4*>(src + (size_t)mm * NF + b * 64 + c4)
                : make_float4(0.f, 0.f, 0.f, 0.f);
            float* d = us + ml * 65 + c4;
            d[0] = v.x; d[1] = v.y; d[2] = v.z; d[3] = v.w;
        }
        __syncthreads();
        const float* wk = ws + oh * 32;
#pragma unroll 4
        for (int jc = 0; jc < 64; jc++) {
            unsigned long long u0 = pack2_dup(us[th * 65 + jc]);
            unsigned long long u1 = pack2_dup(us[(th + 256) * 65 + jc]);
            const ulonglong2* wv =
                reinterpret_cast<const ulonglong2*>(wk + jc * 64);
#pragma unroll
            for (int q = 0; q < 8; q++) {
                ulonglong2 wq = wv[q];      // (w[o0],w[o0+1]),(w[o0+2],w[o0+3])
                acc0[2 * q]     = fma2(wq.x, u0, acc0[2 * q]);
                acc0[2 * q + 1] = fma2(wq.y, u0, acc0[2 * q + 1]);
                acc1[2 * q]     = fma2(wq.x, u1, acc1[2 * q]);
                acc1[2 * q + 1] = fma2(wq.y, u1, acc1[2 * q + 1]);
            }
        }
    }

#pragma unroll
    for (int q = 0; q < 8; q++) {
        int o = oh * 32 + 4 * q;
        float b0 = bias[o], b1 = bias[o + 1], b2 = bias[o + 2], b3 = bias[o + 3];
        float v0, v1, v2, v3;
        if (m0 < MM) {
            unpack2(acc0[2 * q], v0, v1);
            unpack2(acc0[2 * q + 1], v2, v3);
            y[((size_t)b * 64 + o    ) * MM + m0] = v0 + b0;
            y[((size_t)b * 64 + o + 1) * MM + m0] = v1 + b1;
            y[((size_t)b * 64 + o + 2) * MM + m0] = v2 + b2;
            y[((size_t)b * 64 + o + 3) * MM + m0] = v3 + b3;
        }
        if (m1 < MM) {
            unpack2(acc1[2 * q], v0, v1);
            unpack2(acc1[2 * q + 1], v2, v3);
            y[((size_t)b * 64 + o    ) * MM + m1] = v0 + b0;
            y[((size_t)b * 64 + o + 1) * MM + m1] = v1 + b1;
            y[((size_t)b * 64 + o + 2) * MM + m1] = v2 + b2;
            y[((size_t)b * 64 + o + 3) * MM + m1] = v3 + b3;
        }
    }
}

// ---------------- launch ----------------------------------------------------
extern "C" void kernel_launch(void* const* d_in, const int* in_sizes, int n_in,
                              void* d_out, int out_size) {
    const int*   LlI  = (const int*)  d_in[0];   // (2, NNZ): rows then cols
    const float* LlV  = (const float*)d_in[1];
    const int*   LuI  = (const int*)  d_in[2];
    const float* LuV  = (const float*)d_in[3];
    const float* x    = (const float*)d_in[4];
    const float* th   = (const float*)d_in[5];
    const float* bias = (const float*)d_in[6];
    float*       y    = (float*)d_out;
    int nnz = in_sizes[1];                       // Ll_values element count

    float *xt, *p1l, *p2l, *p1u, *p2u, *w;
    cudaGetSymbolAddress((void**)&xt,  g_xt);
    cudaGetSymbolAddress((void**)&p1l, g_p1l);
    cudaGetSymbolAddress((void**)&p2l, g_p2l);
    cudaGetSymbolAddress((void**)&p1u, g_p1u);
    cudaGetSymbolAddress((void**)&p2u, g_p2u);
    cudaGetSymbolAddress((void**)&w,   g_w);

    int  *cnt, *rsb, *bsum;
    int2 *ents;
    cudaGetSymbolAddress((void**)&cnt,  g_cnt);
    cudaGetSymbolAddress((void**)&rsb,  g_rs);
    cudaGetSymbolAddress((void**)&bsum, g_bsum);
    cudaGetSymbolAddress((void**)&ents, g_ents);

    cudaMemsetAsync(cnt, 0, 2 * MM * sizeof(int));

    int eb2 = (2 * nnz + 255) / 256;
    int nScanBlk = (MM + 1023) / 1024;           // 98
    hist_dual_kernel<<<eb2, 256>>>(LlI, LuI, nnz, cnt);
    scanA_kernel<<<dim3(nScanBlk, 2), 1024>>>(cnt, rsb, bsum, MM);
    scanB_kernel<<<2, 128>>>(bsum, nScanBlk);
    scanC_kernel<<<dim3(nScanBlk, 2), 1024>>>(rsb, cnt, bsum, MM, nnz);
    scatter_dual_kernel<<<eb2, 256>>>(LlI, LuI, LlV, LuV, cnt, ents, nnz);

    transpose_kernel<<<dim3(MM / 32, NF / 32), dim3(32, 8)>>>(x, xt);
    wprep_kernel<<<(KTOT * 64 * 64 + 255) / 256, 256>>>(th, w);

    int spmmBlocks = (2 * MM * 32 + 255) / 256;
    spmm_dual_kernel<<<spmmBlocks, 256>>>(rsb, ents, xt,  xt,  p1l, p1u);   // pass A
    spmm_dual_kernel<<<spmmBlocks, 256>>>(rsb, ents, p1l, p1u, p2l, p2u);   // pass B

    cudaFuncSetAttribute(combine_kernel,
                         cudaFuncAttributeMaxDynamicSharedMemorySize, CMB_SMEM_BYTES);
    combine_kernel<<<dim3((MM + CMB_TILE - 1) / CMB_TILE, 2), CMB_THREADS,
                     CMB_SMEM_BYTES>>>(bias, y);
}

// round 6
// speedup vs baseline: 2.0143x; 1.0862x over previous
#include <cuda_runtime.h>
#include <cstdint>

#define MM    100000   // simplices
#define NF    128      // B * C_IN features per simplex
#define KTOT  5        // [x, Ll x, Ll^2 x, Lu x, Lu^2 x]
#define ELLW  48       // ELL row capacity (Poisson(8) tail @48 ~ 1e-20)

// ---------------- scratch (device globals: no allocations allowed) ----------
__device__ __align__(16) float g_xt [(size_t)MM * NF];
__device__ __align__(16) float g_p1l[(size_t)MM * NF];
__device__ __align__(16) float g_p2l[(size_t)MM * NF];
__device__ __align__(16) float g_p1u[(size_t)MM * NF];
__device__ __align__(16) float g_p2u[(size_t)MM * NF];
__device__ __align__(16) float g_w  [KTOT * 64 * 64];          // Wt[j][o]
__device__ int   g_cnt [2 * MM];                               // ELL row counts
__device__ __align__(16) int2 g_ents[(size_t)2 * MM * ELLW];   // {col, val} ELL

// ---------------- packed fp32x2 helpers (sm_100+) ---------------------------
__device__ __forceinline__ unsigned long long pack2_dup(float v) {
    unsigned long long r; uint32_t u = __float_as_uint(v);
    asm("mov.b64 %0, {%1,%2};" : "=l"(r) : "r"(u), "r"(u));
    return r;
}
__device__ __forceinline__ unsigned long long fma2(unsigned long long a,
                                                   unsigned long long b,
                                                   unsigned long long c) {
    unsigned long long d;
    asm("fma.rn.f32x2 %0, %1, %2, %3;" : "=l"(d) : "l"(a), "l"(b), "l"(c));
    return d;
}
__device__ __forceinline__ void unpack2(unsigned long long v, float& lo, float& hi) {
    uint32_t a, b;
    asm("mov.b64 {%0,%1}, %2;" : "=r"(a), "=r"(b) : "l"(v));
    lo = __uint_as_float(a); hi = __uint_as_float(b);
}
// 4-byte cp.async: only 4B alignment required; szr=0 zero-fills
__device__ __forceinline__ void cp_async4(uint32_t dst, const void* src, int szr) {
    asm volatile("cp.async.ca.shared.global [%0], [%1], 4, %2;"
                 :: "r"(dst), "l"(src), "r"(szr));
}
#define CP_COMMIT() asm volatile("cp.async.commit_group;" ::: "memory")
#define CP_WAIT1()  asm volatile("cp.async.wait_group 1;" ::: "memory")
#define CP_WAIT0()  asm volatile("cp.async.wait_group 0;" ::: "memory")

// ---------------- 1) transpose x (128, M) -> xt (M, 128) --------------------
__global__ void transpose_kernel(const float* __restrict__ x, float* __restrict__ xt) {
    __shared__ float tile[32][33];
    int mBase = blockIdx.x * 32, fBase = blockIdx.y * 32;
    int tx = threadIdx.x, ty = threadIdx.y;
#pragma unroll
    for (int i = 0; i < 32; i += 8)
        tile[ty + i][tx] = x[(size_t)(fBase + ty + i) * MM + mBase + tx];
    __syncthreads();
#pragma unroll
    for (int i = 0; i < 32; i += 8)
        xt[(size_t)(mBase + ty + i) * NF + fBase + tx] = tile[tx][ty + i];
}

// ---------------- ELL build: single scatter pass -----------------------------
__global__ void scatter_ell_kernel(const int* __restrict__ LlI, const int* __restrict__ LuI,
                                   const float* __restrict__ LlV, const float* __restrict__ LuV,
                                   int* __restrict__ cnt, int2* __restrict__ ents, int nnz) {
    int e = blockIdx.x * blockDim.x + threadIdx.x;
    if (e >= 2 * nnz) return;
    int s = (e >= nnz);
    int el = e - s * nnz;
    int r   = s ? LuI[el]       : LlI[el];
    int c   = s ? LuI[el + nnz] : LlI[el + nnz];
    float v = s ? LuV[el]       : LlV[el];
    int idx = atomicAdd(&cnt[s * MM + r], 1);
    if (idx < ELLW)
        ents[(size_t)(s * MM + r) * ELLW + idx] = make_int2(c, __float_as_int(v));
}

// ---------------- 2) dual ELL SpMM: warp per row, MLP-4 inner loop ----------
__global__ void spmm_dual_kernel(const int* __restrict__ cnt, const int2* __restrict__ entsB,
                                 const float* __restrict__ in0, const float* __restrict__ in1,
                                 float* __restrict__ out0, float* __restrict__ out1) {
    int w = (blockIdx.x * blockDim.x + threadIdx.x) >> 5;
    if (w >= 2 * MM) return;
    int s = (w >= MM);
    int r = w - s * MM;
    int lane = threadIdx.x & 31;
    const float* in  = s ? in1 : in0;
    float*       out = s ? out1 : out0;

    int n = __ldg(cnt + s * MM + r);
    n = n < ELLW ? n : ELLW;
    const int2* ents = entsB + (size_t)(s * MM + r) * ELLW;
    int j = 0;
    float ax = 0.f, ay = 0.f, az = 0.f, aw = 0.f;

    for (; n >= 4; n -= 4, j += 4) {
        int2 e0 = __ldg(ents + j);
        int2 e1 = __ldg(ents + j + 1);
        int2 e2 = __ldg(ents + j + 2);
        int2 e3 = __ldg(ents + j + 3);
        float4 g0 = __ldg(reinterpret_cast<const float4*>(in + (size_t)e0.x * NF) + lane);
        float4 g1 = __ldg(reinterpret_cast<const float4*>(in + (size_t)e1.x * NF) + lane);
        float4 g2 = __ldg(reinterpret_cast<const float4*>(in + (size_t)e2.x * NF) + lane);
        float4 g3 = __ldg(reinterpret_cast<const float4*>(in + (size_t)e3.x * NF) + lane);
        float v0 = __int_as_float(e0.y), v1 = __int_as_float(e1.y);
        float v2 = __int_as_float(e2.y), v3 = __int_as_float(e3.y);
        ax += v0 * g0.x; ay += v0 * g0.y; az += v0 * g0.z; aw += v0 * g0.w;
        ax += v1 * g1.x; ay += v1 * g1.y; az += v1 * g1.z; aw += v1 * g1.w;
        ax += v2 * g2.x; ay += v2 * g2.y; az += v2 * g2.z; aw += v2 * g2.w;
        ax += v3 * g3.x; ay += v3 * g3.y; az += v3 * g3.z; aw += v3 * g3.w;
    }
    for (; n > 0; n--, j++) {
        int2 ev = __ldg(ents + j);
        float v = __int_as_float(ev.y);
        float4 g = __ldg(reinterpret_cast<const float4*>(in + (size_t)ev.x * NF) + lane);
        ax += v * g.x; ay += v * g.y; az += v * g.z; aw += v * g.w;
    }
    float4 o = make_float4(ax, ay, az, aw);
    *reinterpret_cast<float4*>(out + (size_t)r * NF + lane * 4) = o;
}

// ---------------- 3) fold theta -> Wt[j][o] ---------------------------------
__global__ void wprep_kernel(const float* __restrict__ theta, float* __restrict__ w) {
    int i = blockIdx.x * blockDim.x + threadIdx.x;   // i = (k*64+c)*64 + o
    if (i >= KTOT * 64 * 64) return;
    int o = i & 63;
    int c = (i >> 6) & 63;
    int k = i >> 12;
    const int kmap[KTOT] = {0, 1, 2, 4, 5};
    float v = theta[(o * 64 + c) * 6 + kmap[k]];
    if (k == 0) v += theta[(o * 64 + c) * 6 + 3];
    w[i] = v;
}

// ---------------- 4) combine v3: cp.async double-buffered half-k phases -----
// 512 threads = 2 o-halves x 256 m slots, 2 m per thread, 32 u64 accs.
// 10 phases (5 k x 2 half-channel groups); stage phase p+1 while computing p.
// smem: W all-k 80KB + 2 x us[512][33] 132KB = 212KB.
// cp.async.4 per element: stride 33 stays conflict-free on LDS, alignment OK.
#define CMB_THREADS 512
#define CMB_TILE    512
#define US_STRIDE   33
#define WS_FLOATS   (KTOT * 64 * 64)
#define USB_FLOATS  (CMB_TILE * US_STRIDE)
#define CMB_SMEM_BYTES ((WS_FLOATS + 2 * USB_FLOATS) * 4)

__device__ __forceinline__ const float* bufsel(int k) {
    switch (k) {
        case 0:  return g_xt;
        case 1:  return g_p1l;
        case 2:  return g_p2l;
        case 3:  return g_p1u;
        default: return g_p2u;
    }
}

__global__ __launch_bounds__(CMB_THREADS, 1)
void combine_kernel(const float* __restrict__ bias, float* __restrict__ y) {
    extern __shared__ float smem[];
    float* ws  = smem;                       // [320][64]
    float* usb = smem + WS_FLOATS;           // 2 x [512][33]

    int t  = threadIdx.x;
    int th = t & 255;                        // m slot
    int oh = t >> 8;                         // output half
    int b  = blockIdx.y;
    int mBase = blockIdx.x * CMB_TILE;
    int m0 = mBase + th, m1 = m0 + 256;

    // stage all W (80KB) via float4
    {
        const float4* wsrc = reinterpret_cast<const float4*>(g_w);
        float4* wdst = reinterpret_cast<float4*>(ws);
#pragma unroll
        for (int i = 0; i < WS_FLOATS / 4; i += CMB_THREADS)
            wdst[i + t] = wsrc[i + t];
    }

    unsigned long long acc0[16], acc1[16];
#pragma unroll
    for (int p = 0; p < 16; p++) { acc0[p] = 0ull; acc1[p] = 0ull; }

    // stage phase p into buffer p&1: 512 rows x 32 channels, 4B cp.async each.
    // lane-consecutive channels: gmem 128B coalesced runs, STS conflict-free.
    auto stage = [&](int p) {
        int k = p >> 1, half = p & 1;
        const float* src = bufsel(k) + b * 64 + half * 32;
        float* dbuf = usb + (p & 1) * USB_FLOATS;
#pragma unroll
        for (int j = 0; j < 32; j++) {
            int i  = t + j * CMB_THREADS;
            int ml = i >> 5, c = i & 31;     // row, channel
            int mm = mBase + ml;
            int ok = (mm < MM);
            const float* sp = src + (size_t)(ok ? mm : 0) * NF + c;
            uint32_t d = (uint32_t)__cvta_generic_to_shared(dbuf + ml * US_STRIDE + c);
            cp_async4(d, sp, ok ? 4 : 0);    // zero-fill OOB rows
        }
    };

    stage(0);
    CP_COMMIT();

#pragma unroll 1
    for (int p = 0; p < 2 * KTOT; p++) {
        if (p < 2 * KTOT - 1) {
            stage(p + 1);
            CP_COMMIT();
            CP_WAIT1();
        } else {
            CP_WAIT0();
        }
        __syncthreads();                      // phase-p buffer visible block-wide

        int k = p >> 1, half = p & 1;
        const float* us = usb + (p & 1) * USB_FLOATS;
        const float* wkbase = ws + k * 4096 + half * 32 * 64 + oh * 32;
#pragma unroll 4
        for (int jc = 0; jc < 32; jc++) {
            unsigned long long u0 = pack2_dup(us[th * US_STRIDE + jc]);
            unsigned long long u1 = pack2_dup(us[(th + 256) * US_STRIDE + jc]);
            const ulonglong2* wv =
                reinterpret_cast<const ulonglong2*>(wkbase + jc * 64);
#pragma unroll
            for (int q = 0; q < 8; q++) {
                ulonglong2 wq = wv[q];
                acc0[2 * q]     = fma2(wq.x, u0, acc0[2 * q]);
                acc0[2 * q + 1] = fma2(wq.y, u0, acc0[2 * q + 1]);
                acc1[2 * q]     = fma2(wq.x, u1, acc1[2 * q]);
                acc1[2 * q + 1] = fma2(wq.y, u1, acc1[2 * q + 1]);
            }
        }
        __syncthreads();                      // done reading before buffer reuse
    }

#pragma unroll
    for (int q = 0; q < 8; q++) {
        int o = oh * 32 + 4 * q;
        float b0 = bias[o], b1 = bias[o + 1], b2 = bias[o + 2], b3 = bias[o + 3];
        float v0, v1, v2, v3;
        if (m0 < MM) {
            unpack2(acc0[2 * q], v0, v1);
            unpack2(acc0[2 * q + 1], v2, v3);
            y[((size_t)b * 64 + o    ) * MM + m0] = v0 + b0;
            y[((size_t)b * 64 + o + 1) * MM + m0] = v1 + b1;
            y[((size_t)b * 64 + o + 2) * MM + m0] = v2 + b2;
            y[((size_t)b * 64 + o + 3) * MM + m0] = v3 + b3;
        }
        if (m1 < MM) {
            unpack2(acc1[2 * q], v0, v1);
            unpack2(acc1[2 * q + 1], v2, v3);
            y[((size_t)b * 64 + o    ) * MM + m1] = v0 + b0;
            y[((size_t)b * 64 + o + 1) * MM + m1] = v1 + b1;
            y[((size_t)b * 64 + o + 2) * MM + m1] = v2 + b2;
            y[((size_t)b * 64 + o + 3) * MM + m1] = v3 + b3;
        }
    }
}

// ---------------- launch ----------------------------------------------------
extern "C" void kernel_launch(void* const* d_in, const int* in_sizes, int n_in,
                              void* d_out, int out_size) {
    const int*   LlI  = (const int*)  d_in[0];   // (2, NNZ): rows then cols
    const float* LlV  = (const float*)d_in[1];
    const int*   LuI  = (const int*)  d_in[2];
    const float* LuV  = (const float*)d_in[3];
    const float* x    = (const float*)d_in[4];
    const float* th   = (const float*)d_in[5];
    const float* bias = (const float*)d_in[6];
    float*       y    = (float*)d_out;
    int nnz = in_sizes[1];                       // Ll_values element count

    float *xt, *p1l, *p2l, *p1u, *p2u, *w;
    cudaGetSymbolAddress((void**)&xt,  g_xt);
    cudaGetSymbolAddress((void**)&p1l, g_p1l);
    cudaGetSymbolAddress((void**)&p2l, g_p2l);
    cudaGetSymbolAddress((void**)&p1u, g_p1u);
    cudaGetSymbolAddress((void**)&p2u, g_p2u);
    cudaGetSymbolAddress((void**)&w,   g_w);

    int  *cnt;
    int2 *ents;
    cudaGetSymbolAddress((void**)&cnt,  g_cnt);
    cudaGetSymbolAddress((void**)&ents, g_ents);

    cudaMemsetAsync(cnt, 0, 2 * MM * sizeof(int));

    int eb2 = (2 * nnz + 255) / 256;
    scatter_ell_kernel<<<eb2, 256>>>(LlI, LuI, LlV, LuV, cnt, ents, nnz);

    transpose_kernel<<<dim3(MM / 32, NF / 32), dim3(32, 8)>>>(x, xt);
    wprep_kernel<<<(KTOT * 64 * 64 + 255) / 256, 256>>>(th, w);

    int spmmBlocks = (2 * MM * 32 + 255) / 256;
    spmm_dual_kernel<<<spmmBlocks, 256>>>(cnt, ents, xt,  xt,  p1l, p1u);   // pass A
    spmm_dual_kernel<<<spmmBlocks, 256>>>(cnt, ents, p1l, p1u, p2l, p2u);   // pass B

    cudaFuncSetAttribute(combine_kernel,
                         cudaFuncAttributeMaxDynamicSharedMemorySize, CMB_SMEM_BYTES);
    combine_kernel<<<dim3((MM + CMB_TILE - 1) / CMB_TILE, 2), CMB_THREADS,
                     CMB_SMEM_BYTES>>>(bias, y);
}

// round 7
// speedup vs baseline: 2.1251x; 1.0550x over previous
#include <cuda_runtime.h>
#include <cstdint>

#define MM    100000   // simplices
#define NF    128      // B * C_IN features per simplex
#define KTOT  5        // [x, Ll x, Ll^2 x, Lu x, Lu^2 x]
#define ELLW  48       // ELL row capacity (Poisson(8) tail @48 ~ 1e-20)

// ---------------- scratch (device globals: no allocations allowed) ----------
__device__ __align__(16) float g_xt [(size_t)MM * NF];
__device__ __align__(16) float g_p1l[(size_t)MM * NF];
__device__ __align__(16) float g_p2l[(size_t)MM * NF];
__device__ __align__(16) float g_p1u[(size_t)MM * NF];
__device__ __align__(16) float g_p2u[(size_t)MM * NF];
__device__ __align__(16) float g_w  [KTOT * 64 * 64];          // Wt[j][o]
__device__ int   g_cnt [2 * MM];                               // ELL row counts
__device__ __align__(16) int2 g_ents[(size_t)2 * MM * ELLW];   // {col, val} ELL

// ---------------- packed fp32x2 helpers (sm_100+) ---------------------------
__device__ __forceinline__ unsigned long long pack2_dup(float v) {
    unsigned long long r; uint32_t u = __float_as_uint(v);
    asm("mov.b64 %0, {%1,%2};" : "=l"(r) : "r"(u), "r"(u));
    return r;
}
__device__ __forceinline__ unsigned long long fma2(unsigned long long a,
                                                   unsigned long long b,
                                                   unsigned long long c) {
    unsigned long long d;
    asm("fma.rn.f32x2 %0, %1, %2, %3;" : "=l"(d) : "l"(a), "l"(b), "l"(c));
    return d;
}
__device__ __forceinline__ void unpack2(unsigned long long v, float& lo, float& hi) {
    uint32_t a, b;
    asm("mov.b64 {%0,%1}, %2;" : "=r"(a), "=r"(b) : "l"(v));
    lo = __uint_as_float(a); hi = __uint_as_float(b);
}
__device__ __forceinline__ void cp_async4(uint32_t dst, const void* src, int szr) {
    asm volatile("cp.async.ca.shared.global [%0], [%1], 4, %2;"
                 :: "r"(dst), "l"(src), "r"(szr));
}
__device__ __forceinline__ void cp_async16(uint32_t dst, const void* src) {
    asm volatile("cp.async.cg.shared.global [%0], [%1], 16;"
                 :: "r"(dst), "l"(src));
}
#define CP_COMMIT() asm volatile("cp.async.commit_group;" ::: "memory")
#define CP_WAIT1()  asm volatile("cp.async.wait_group 1;" ::: "memory")
#define CP_WAIT0()  asm volatile("cp.async.wait_group 0;" ::: "memory")

// ---------------- 1) transpose x (128, M) -> xt (M, 128) --------------------
__global__ void transpose_kernel(const float* __restrict__ x, float* __restrict__ xt) {
    __shared__ float tile[32][33];
    int mBase = blockIdx.x * 32, fBase = blockIdx.y * 32;
    int tx = threadIdx.x, ty = threadIdx.y;
#pragma unroll
    for (int i = 0; i < 32; i += 8)
        tile[ty + i][tx] = x[(size_t)(fBase + ty + i) * MM + mBase + tx];
    __syncthreads();
#pragma unroll
    for (int i = 0; i < 32; i += 8)
        xt[(size_t)(mBase + ty + i) * NF + fBase + tx] = tile[tx][ty + i];
}

// ---------------- ELL build: single scatter pass -----------------------------
__global__ void scatter_ell_kernel(const int* __restrict__ LlI, const int* __restrict__ LuI,
                                   const float* __restrict__ LlV, const float* __restrict__ LuV,
                                   int* __restrict__ cnt, int2* __restrict__ ents, int nnz) {
    int e = blockIdx.x * blockDim.x + threadIdx.x;
    if (e >= 2 * nnz) return;
    int s = (e >= nnz);
    int el = e - s * nnz;
    int r   = s ? LuI[el]       : LlI[el];
    int c   = s ? LuI[el + nnz] : LlI[el + nnz];
    float v = s ? LuV[el]       : LlV[el];
    int idx = atomicAdd(&cnt[s * MM + r], 1);
    if (idx < ELLW)
        ents[(size_t)(s * MM + r) * ELLW + idx] = make_int2(c, __float_as_int(v));
}

// ---------------- 2) dual ELL SpMM: warp per row, MLP-4 inner loop ----------
__global__ void spmm_dual_kernel(const int* __restrict__ cnt, const int2* __restrict__ entsB,
                                 const float* __restrict__ in0, const float* __restrict__ in1,
                                 float* __restrict__ out0, float* __restrict__ out1) {
    int w = (blockIdx.x * blockDim.x + threadIdx.x) >> 5;
    if (w >= 2 * MM) return;
    int s = (w >= MM);
    int r = w - s * MM;
    int lane = threadIdx.x & 31;
    const float* in  = s ? in1 : in0;
    float*       out = s ? out1 : out0;

    int n = __ldg(cnt + s * MM + r);
    n = n < ELLW ? n : ELLW;
    const int2* ents = entsB + (size_t)(s * MM + r) * ELLW;
    int j = 0;
    float ax = 0.f, ay = 0.f, az = 0.f, aw = 0.f;

    for (; n >= 4; n -= 4, j += 4) {
        int2 e0 = __ldg(ents + j);
        int2 e1 = __ldg(ents + j + 1);
        int2 e2 = __ldg(ents + j + 2);
        int2 e3 = __ldg(ents + j + 3);
        float4 g0 = __ldg(reinterpret_cast<const float4*>(in + (size_t)e0.x * NF) + lane);
        float4 g1 = __ldg(reinterpret_cast<const float4*>(in + (size_t)e1.x * NF) + lane);
        float4 g2 = __ldg(reinterpret_cast<const float4*>(in + (size_t)e2.x * NF) + lane);
        float4 g3 = __ldg(reinterpret_cast<const float4*>(in + (size_t)e3.x * NF) + lane);
        float v0 = __int_as_float(e0.y), v1 = __int_as_float(e1.y);
        float v2 = __int_as_float(e2.y), v3 = __int_as_float(e3.y);
        ax += v0 * g0.x; ay += v0 * g0.y; az += v0 * g0.z; aw += v0 * g0.w;
        ax += v1 * g1.x; ay += v1 * g1.y; az += v1 * g1.z; aw += v1 * g1.w;
        ax += v2 * g2.x; ay += v2 * g2.y; az += v2 * g2.z; aw += v2 * g2.w;
        ax += v3 * g3.x; ay += v3 * g3.y; az += v3 * g3.z; aw += v3 * g3.w;
    }
    for (; n > 0; n--, j++) {
        int2 ev = __ldg(ents + j);
        float v = __int_as_float(ev.y);
        float4 g = __ldg(reinterpret_cast<const float4*>(in + (size_t)ev.x * NF) + lane);
        ax += v * g.x; ay += v * g.y; az += v * g.z; aw += v * g.w;
    }
    float4 o = make_float4(ax, ay, az, aw);
    *reinterpret_cast<float4*>(out + (size_t)r * NF + lane * 4) = o;
}

// ---------------- 3) fold theta -> Wt[j][o] ---------------------------------
__global__ void wprep_kernel(const float* __restrict__ theta, float* __restrict__ w) {
    int i = blockIdx.x * blockDim.x + threadIdx.x;   // i = (k*64+c)*64 + o
    if (i >= KTOT * 64 * 64) return;
    int o = i & 63;
    int c = (i >> 6) & 63;
    int k = i >> 12;
    const int kmap[KTOT] = {0, 1, 2, 4, 5};
    float v = theta[(o * 64 + c) * 6 + kmap[k]];
    if (k == 0) v += theta[(o * 64 + c) * 6 + 3];
    w[i] = v;
}

// ---------------- 4) combine v4: 2 CTAs/SM, double-buffered W slice + us ----
// 256 threads = 2 o-halves x 128 m slots, 2 m per thread, 32 u64 accs.
// 10 phases (5 k x 2 channel halves). Per phase stage: W half-slice [32][64]
// (8KB, cp.async.16) + us [256][32] (32KB, cp.async.4, stride 33).
// smem: 2x2048 + 2x(256x33) floats = 82KB -> 2 CTAs/SM, so one CTA's
// barrier/staging phases are covered by the other's fma2 stream.
#define CMB_THREADS 256
#define CMB_TILE    256
#define US_STRIDE   33
#define WSB_FLOATS  (32 * 64)
#define USB_FLOATS  (CMB_TILE * US_STRIDE)
#define CMB_SMEM_BYTES ((2 * WSB_FLOATS + 2 * USB_FLOATS) * 4)

__device__ __forceinline__ const float* bufsel(int k) {
    switch (k) {
        case 0:  return g_xt;
        case 1:  return g_p1l;
        case 2:  return g_p2l;
        case 3:  return g_p1u;
        default: return g_p2u;
    }
}

__global__ __launch_bounds__(CMB_THREADS, 2)
void combine_kernel(const float* __restrict__ bias, float* __restrict__ y) {
    extern __shared__ float smem[];
    float* wsb = smem;                        // 2 x [32][64]
    float* usb = smem + 2 * WSB_FLOATS;       // 2 x [256][33]

    int t  = threadIdx.x;
    int th = t & 127;                         // m slot
    int oh = t >> 7;                          // output half
    int b  = blockIdx.y;
    int mBase = blockIdx.x * CMB_TILE;
    int m0 = mBase + th, m1 = m0 + 128;

    unsigned long long acc0[16], acc1[16];
#pragma unroll
    for (int p = 0; p < 16; p++) { acc0[p] = 0ull; acc1[p] = 0ull; }

    // stage phase p into buffer p&1
    auto stage = [&](int p) {
        int k = p >> 1, half = p & 1, bufi = p & 1;
        // W half-slice: rows jc in [0,32) of Wt[k,half] -> 2048 floats
        const float* wsrc = g_w + k * 4096 + half * 2048;
        float* wdst = wsb + bufi * WSB_FLOATS;
#pragma unroll
        for (int j = 0; j < 2; j++) {
            int i = t + j * CMB_THREADS;       // 0..511 chunks of 16B
            uint32_t d = (uint32_t)__cvta_generic_to_shared(wdst + i * 4);
            cp_async16(d, wsrc + i * 4);
        }
        // us: 256 rows x 32 channels; stride 33 (conflict-free reads)
        const float* src = bufsel(k) + b * 64 + half * 32;
        float* dbuf = usb + bufi * USB_FLOATS;
#pragma unroll
        for (int j = 0; j < 32; j++) {
            int i  = t + j * CMB_THREADS;
            int ml = i >> 5, c = i & 31;
            int mm = mBase + ml;
            int ok = (mm < MM);
            const float* sp = src + (size_t)(ok ? mm : 0) * NF + c;
            uint32_t d = (uint32_t)__cvta_generic_to_shared(dbuf + ml * US_STRIDE + c);
            cp_async4(d, sp, ok ? 4 : 0);
        }
    };

    stage(0);
    CP_COMMIT();

#pragma unroll 1
    for (int p = 0; p < 2 * KTOT; p++) {
        if (p < 2 * KTOT - 1) {
            stage(p + 1);
            CP_COMMIT();
            CP_WAIT1();
        } else {
            CP_WAIT0();
        }
        __syncthreads();                      // phase-p buffers visible block-wide

        const float* us = usb + (p & 1) * USB_FLOATS;
        const float* wk = wsb + (p & 1) * WSB_FLOATS + oh * 32;
#pragma unroll 4
        for (int jc = 0; jc < 32; jc++) {
            unsigned long long u0 = pack2_dup(us[th * US_STRIDE + jc]);
            unsigned long long u1 = pack2_dup(us[(th + 128) * US_STRIDE + jc]);
            const ulonglong2* wv =
                reinterpret_cast<const ulonglong2*>(wk + jc * 64);
#pragma unroll
            for (int q = 0; q < 8; q++) {
                ulonglong2 wq = wv[q];
                acc0[2 * q]     = fma2(wq.x, u0, acc0[2 * q]);
                acc0[2 * q + 1] = fma2(wq.y, u0, acc0[2 * q + 1]);
                acc1[2 * q]     = fma2(wq.x, u1, acc1[2 * q]);
                acc1[2 * q + 1] = fma2(wq.y, u1, acc1[2 * q + 1]);
            }
        }
        __syncthreads();                      // done reading before buffer reuse
    }

#pragma unroll
    for (int q = 0; q < 8; q++) {
        int o = oh * 32 + 4 * q;
        float b0 = bias[o], b1 = bias[o + 1], b2 = bias[o + 2], b3 = bias[o + 3];
        float v0, v1, v2, v3;
        if (m0 < MM) {
            unpack2(acc0[2 * q], v0, v1);
            unpack2(acc0[2 * q + 1], v2, v3);
            y[((size_t)b * 64 + o    ) * MM + m0] = v0 + b0;
            y[((size_t)b * 64 + o + 1) * MM + m0] = v1 + b1;
            y[((size_t)b * 64 + o + 2) * MM + m0] = v2 + b2;
            y[((size_t)b * 64 + o + 3) * MM + m0] = v3 + b3;
        }
        if (m1 < MM) {
            unpack2(acc1[2 * q], v0, v1);
            unpack2(acc1[2 * q + 1], v2, v3);
            y[((size_t)b * 64 + o    ) * MM + m1] = v0 + b0;
            y[((size_t)b * 64 + o + 1) * MM + m1] = v1 + b1;
            y[((size_t)b * 64 + o + 2) * MM + m1] = v2 + b2;
            y[((size_t)b * 64 + o + 3) * MM + m1] = v3 + b3;
        }
    }
}

// ---------------- launch ----------------------------------------------------
extern "C" void kernel_launch(void* const* d_in, const int* in_sizes, int n_in,
                              void* d_out, int out_size) {
    const int*   LlI  = (const int*)  d_in[0];   // (2, NNZ): rows then cols
    const float* LlV  = (const float*)d_in[1];
    const int*   LuI  = (const int*)  d_in[2];
    const float* LuV  = (const float*)d_in[3];
    const float* x    = (const float*)d_in[4];
    const float* th   = (const float*)d_in[5];
    const float* bias = (const float*)d_in[6];
    float*       y    = (float*)d_out;
    int nnz = in_sizes[1];                       // Ll_values element count

    float *xt, *p1l, *p2l, *p1u, *p2u, *w;
    cudaGetSymbolAddress((void**)&xt,  g_xt);
    cudaGetSymbolAddress((void**)&p1l, g_p1l);
    cudaGetSymbolAddress((void**)&p2l, g_p2l);
    cudaGetSymbolAddress((void**)&p1u, g_p1u);
    cudaGetSymbolAddress((void**)&p2u, g_p2u);
    cudaGetSymbolAddress((void**)&w,   g_w);

    int  *cnt;
    int2 *ents;
    cudaGetSymbolAddress((void**)&cnt,  g_cnt);
    cudaGetSymbolAddress((void**)&ents, g_ents);

    cudaMemsetAsync(cnt, 0, 2 * MM * sizeof(int));

    int eb2 = (2 * nnz + 255) / 256;
    scatter_ell_kernel<<<eb2, 256>>>(LlI, LuI, LlV, LuV, cnt, ents, nnz);

    transpose_kernel<<<dim3(MM / 32, NF / 32), dim3(32, 8)>>>(x, xt);
    wprep_kernel<<<(KTOT * 64 * 64 + 255) / 256, 256>>>(th, w);

    int spmmBlocks = (2 * MM * 32 + 255) / 256;
    spmm_dual_kernel<<<spmmBlocks, 256>>>(cnt, ents, xt,  xt,  p1l, p1u);   // pass A
    spmm_dual_kernel<<<spmmBlocks, 256>>>(cnt, ents, p1l, p1u, p2l, p2u);   // pass B

    cudaFuncSetAttribute(combine_kernel,
                         cudaFuncAttributeMaxDynamicSharedMemorySize, CMB_SMEM_BYTES);
    combine_kernel<<<dim3((MM + CMB_TILE - 1) / CMB_TILE, 2), CMB_THREADS,
                     CMB_SMEM_BYTES>>>(bias, y);
}

// round 9
// speedup vs baseline: 2.7632x; 1.3002x over previous
#include <cuda_runtime.h>
#include <cuda_bf16.h>
#include <cstdint>

#define MM    100000   // simplices
#define NF    128      // B * C_IN features per simplex
#define KTOT  5        // [x, Ll x, Ll^2 x, Lu x, Lu^2 x]
#define ELLW  48       // ELL row capacity
#define UBF_SLOT ((size_t)MM * 256)   // uint16 elems per k-buffer: [hi 128 | lo 128]

// ---------------- scratch (device globals: no allocations allowed) ----------
__device__ __align__(16) float    g_xt [(size_t)MM * NF];
__device__ __align__(16) float    g_p1l[(size_t)MM * NF];
__device__ __align__(16) float    g_p1u[(size_t)MM * NF];
__device__ __align__(16) uint16_t g_ubf[(size_t)KTOT * MM * 256];  // bf16 hi/lo, 256MB
__device__ __align__(16) uint2    g_wfrag[2 * 20 * 8 * 32];        // B frags, 80KB
__device__ int   g_cnt [2 * MM];
__device__ __align__(16) int2 g_ents[(size_t)2 * MM * ELLW];

// ---------------- helpers ----------------------------------------------------
__device__ __forceinline__ uint32_t smem_u32(const void* p) {
    uint32_t a;
    asm("{ .reg .u64 t; cvta.to.shared.u64 t, %1; cvt.u32.u64 %0, t; }"
        : "=r"(a) : "l"(p));
    return a;
}
__device__ __forceinline__ void cp_async16(uint32_t dst, const void* src, int szr) {
    asm volatile("cp.async.cg.shared.global [%0], [%1], 16, %2;"
                 :: "r"(dst), "l"(src), "r"(szr));
}
#define CP_COMMIT() asm volatile("cp.async.commit_group;" ::: "memory")
#define CP_WAIT1()  asm volatile("cp.async.wait_group 1;" ::: "memory")
#define CP_WAIT0()  asm volatile("cp.async.wait_group 0;" ::: "memory")

__device__ __forceinline__ void ldm_x4(uint32_t* r, uint32_t addr) {
    asm volatile("ldmatrix.sync.aligned.m8n8.x4.shared.b16 {%0,%1,%2,%3}, [%4];"
                 : "=r"(r[0]), "=r"(r[1]), "=r"(r[2]), "=r"(r[3]) : "r"(addr));
}
__device__ __forceinline__ void mma16816(float* c, const uint32_t* a,
                                         uint32_t b0, uint32_t b1) {
    asm volatile("mma.sync.aligned.m16n8k16.row.col.f32.bf16.bf16.f32 "
                 "{%0,%1,%2,%3}, {%4,%5,%6,%7}, {%8,%9}, {%0,%1,%2,%3};"
                 : "+f"(c[0]), "+f"(c[1]), "+f"(c[2]), "+f"(c[3])
                 : "r"(a[0]), "r"(a[1]), "r"(a[2]), "r"(a[3]), "r"(b0), "r"(b1));
}
__device__ __forceinline__ uint16_t bf_bits(__nv_bfloat16 h) {
    return *reinterpret_cast<uint16_t*>(&h);
}

// ---------------- 1) transpose x (128, M) -> xt fp32 + ubf slot 0 bf16 ------
__global__ void transpose_kernel(const float* __restrict__ x, float* __restrict__ xt) {
    __shared__ float tile[32][33];
    int mBase = blockIdx.x * 32, fBase = blockIdx.y * 32;
    int tx = threadIdx.x, ty = threadIdx.y;
#pragma unroll
    for (int i = 0; i < 32; i += 8)
        tile[ty + i][tx] = x[(size_t)(fBase + ty + i) * MM + mBase + tx];
    __syncthreads();
#pragma unroll
    for (int i = 0; i < 32; i += 8) {
        float v = tile[tx][ty + i];
        int m = mBase + ty + i, f = fBase + tx;
        xt[(size_t)m * NF + f] = v;
        __nv_bfloat16 h = __float2bfloat16_rn(v);
        __nv_bfloat16 l = __float2bfloat16_rn(v - __bfloat162float(h));
        g_ubf[(size_t)m * 256 + f]       = bf_bits(h);
        g_ubf[(size_t)m * 256 + 128 + f] = bf_bits(l);
    }
}

// ---------------- ELL build ---------------------------------------------------
__global__ void scatter_ell_kernel(const int* __restrict__ LlI, const int* __restrict__ LuI,
                                   const float* __restrict__ LlV, const float* __restrict__ LuV,
                                   int* __restrict__ cnt, int2* __restrict__ ents, int nnz) {
    int e = blockIdx.x * blockDim.x + threadIdx.x;
    if (e >= 2 * nnz) return;
    int s = (e >= nnz);
    int el = e - s * nnz;
    int r   = s ? LuI[el]       : LlI[el];
    int c   = s ? LuI[el + nnz] : LlI[el + nnz];
    float v = s ? LuV[el]       : LlV[el];
    int idx = atomicAdd(&cnt[s * MM + r], 1);
    if (idx < ELLW)
        ents[(size_t)(s * MM + r) * ELLW + idx] = make_int2(c, __float_as_int(v));
}

// ---------------- 2) dual ELL SpMM: fp32 out (opt) + bf16 hi/lo out ----------
__global__ void spmm_dual_kernel(const int* __restrict__ cnt, const int2* __restrict__ entsB,
                                 const float* __restrict__ in0, const float* __restrict__ in1,
                                 float* __restrict__ out0, float* __restrict__ out1,
                                 uint16_t* __restrict__ obf0, uint16_t* __restrict__ obf1) {
    int w = (blockIdx.x * blockDim.x + threadIdx.x) >> 5;
    if (w >= 2 * MM) return;
    int s = (w >= MM);
    int r = w - s * MM;
    int lane = threadIdx.x & 31;
    const float* in = s ? in1 : in0;

    int n = __ldg(cnt + s * MM + r);
    n = n < ELLW ? n : ELLW;
    const int2* ents = entsB + (size_t)(s * MM + r) * ELLW;
    int j = 0;
    float ax = 0.f, ay = 0.f, az = 0.f, aw = 0.f;

    for (; n >= 4; n -= 4, j += 4) {
        int2 e0 = __ldg(ents + j);
        int2 e1 = __ldg(ents + j + 1);
        int2 e2 = __ldg(ents + j + 2);
        int2 e3 = __ldg(ents + j + 3);
        float4 g0 = __ldg(reinterpret_cast<const float4*>(in + (size_t)e0.x * NF) + lane);
        float4 g1 = __ldg(reinterpret_cast<const float4*>(in + (size_t)e1.x * NF) + lane);
        float4 g2 = __ldg(reinterpret_cast<const float4*>(in + (size_t)e2.x * NF) + lane);
        float4 g3 = __ldg(reinterpret_cast<const float4*>(in + (size_t)e3.x * NF) + lane);
        float v0 = __int_as_float(e0.y), v1 = __int_as_float(e1.y);
        float v2 = __int_as_float(e2.y), v3 = __int_as_float(e3.y);
        ax += v0 * g0.x; ay += v0 * g0.y; az += v0 * g0.z; aw += v0 * g0.w;
        ax += v1 * g1.x; ay += v1 * g1.y; az += v1 * g1.z; aw += v1 * g1.w;
        ax += v2 * g2.x; ay += v2 * g2.y; az += v2 * g2.z; aw += v2 * g2.w;
        ax += v3 * g3.x; ay += v3 * g3.y; az += v3 * g3.z; aw += v3 * g3.w;
    }
    for (; n > 0; n--, j++) {
        int2 ev = __ldg(ents + j);
        float v = __int_as_float(ev.y);
        float4 g = __ldg(reinterpret_cast<const float4*>(in + (size_t)ev.x * NF) + lane);
        ax += v * g.x; ay += v * g.y; az += v * g.z; aw += v * g.w;
    }

    float* out = s ? out1 : out0;
    if (out)
        *reinterpret_cast<float4*>(out + (size_t)r * NF + lane * 4) =
            make_float4(ax, ay, az, aw);

    // bf16 hi/lo to ubf row [hi 128 | lo 128]
    __nv_bfloat162 h01 = __floats2bfloat162_rn(ax, ay);
    __nv_bfloat162 h23 = __floats2bfloat162_rn(az, aw);
    float2 f01 = __bfloat1622float2(h01);
    float2 f23 = __bfloat1622float2(h23);
    __nv_bfloat162 l01 = __floats2bfloat162_rn(ax - f01.x, ay - f01.y);
    __nv_bfloat162 l23 = __floats2bfloat162_rn(az - f23.x, aw - f23.y);
    uint16_t* ob = (s ? obf1 : obf0) + (size_t)r * 256 + lane * 4;
    *reinterpret_cast<uint2*>(ob) =
        make_uint2(*reinterpret_cast<uint32_t*>(&h01), *reinterpret_cast<uint32_t*>(&h23));
    *reinterpret_cast<uint2*>(ob + 128) =
        make_uint2(*reinterpret_cast<uint32_t*>(&l01), *reinterpret_cast<uint32_t*>(&l23));
}

// ---------------- 3) fold theta -> B fragments (mma register order) ---------
// wfrag[((part*20+kk)*8+oc)*32 + lane] = {pack(B[2tg,o],B[2tg+1,o]),
//                                         pack(B[2tg+8,o],B[2tg+9,o])}
// where B[kloc,o] = Wt[j=kk*16+kloc][o=oc*8+g], part0=hi, part1=lo.
__global__ void wprep_kernel(const float* __restrict__ theta, uint2* __restrict__ wfrag) {
    int i = blockIdx.x * blockDim.x + threadIdx.x;
    if (i >= 2 * 20 * 8 * 32) return;
    int lane = i & 31;
    int oc   = (i >> 5) & 7;
    int kk   = (i >> 8) % 20;
    int part = i / 5120;
    int tg = lane & 3, g = lane >> 2;
    int o = oc * 8 + g;
    const int kmap[KTOT] = {0, 1, 2, 4, 5};
    uint16_t bits[4];
#pragma unroll
    for (int e = 0; e < 4; e++) {
        int j = kk * 16 + 2 * tg + (e & 1) + (e >> 1) * 8;
        int kb = j >> 6, c = j & 63;
        float f = theta[(o * 64 + c) * 6 + kmap[kb]];
        if (kb == 0) f += theta[(o * 64 + c) * 6 + 3];
        __nv_bfloat16 h = __float2bfloat16_rn(f);
        if (part == 0) bits[e] = bf_bits(h);
        else           bits[e] = bf_bits(__float2bfloat16_rn(f - __bfloat162float(h)));
    }
    wfrag[i] = make_uint2((uint32_t)bits[0] | ((uint32_t)bits[1] << 16),
                          (uint32_t)bits[2] | ((uint32_t)bits[3] << 16));
}

// ---------------- 4) combine v6: warp-level bf16 MMA ------------------------
// CTA: 256 thr (8 warps), tile 128m x 64o, batch b. Warp w: m-rows w*16..+15.
// smem: wfrag 80KB + 2 phase-buffers x (hi[128][72] + lo[128][72]) bf16 = 153KB.
// Per phase (k-buffer): stage hi+lo (32KB) cp.async double-buffered; compute
// 4 k16-steps x 8 o-chunks x 3 terms (uh*wh, uh*wl, ul*wh).
#define CMB_THREADS 256
#define SM_WF    0
#define WF_BYTES 81920
#define UB_PLANE 18432                  // 128 rows * 144B
#define UB_BYTES (2 * UB_PLANE)         // hi + lo
#define SM_U0    WF_BYTES
#define CMB_SMEM_BYTES (WF_BYTES + 2 * UB_BYTES)   // 155648

__global__ __launch_bounds__(CMB_THREADS, 1)
void combine_kernel(const float* __restrict__ bias, float* __restrict__ y) {
    extern __shared__ char smem[];
    int t = threadIdx.x;
    int lane = t & 31, w = t >> 5;
    int b = blockIdx.y;
    int mBase = blockIdx.x * 128;

    // stage W fragments (80KB)
    {
        const float4* src = reinterpret_cast<const float4*>(g_wfrag);
        float4* dst = reinterpret_cast<float4*>(smem + SM_WF);
#pragma unroll
        for (int i = t; i < WF_BYTES / 16; i += CMB_THREADS)
            dst[i] = src[i];
    }

    float acc[8][4];
#pragma unroll
    for (int oc = 0; oc < 8; oc++)
#pragma unroll
        for (int e = 0; e < 4; e++) acc[oc][e] = 0.f;

    // stage k-buffer p into phase buffer `buf`
    auto stage = [&](int p, int buf) {
        const char* srcb = reinterpret_cast<const char*>(g_ubf + (size_t)p * UBF_SLOT);
        char* dbase = smem + SM_U0 + buf * UB_BYTES;
#pragma unroll
        for (int jj = 0; jj < 8; jj++) {
            int idx = t + jj * CMB_THREADS;      // 0..2047
            int row = idx >> 4;
            int rem = idx & 15;
            int plane = rem >> 3, ch = rem & 7;
            int mm = mBase + row;
            int ok = (mm < MM);
            const char* sp = srcb + (size_t)(ok ? mm : 0) * 512 + plane * 256 + b * 128 + ch * 16;
            uint32_t d = smem_u32(dbase + plane * UB_PLANE + row * 144 + ch * 16);
            cp_async16(d, sp, ok ? 16 : 0);
        }
    };

    stage(0, 0);
    CP_COMMIT();

    const uint2* wf = reinterpret_cast<const uint2*>(smem + SM_WF);
    int lr = lane & 7;
    int rsel = (lane & 8) ? 8 : 0;
    int csel = (lane & 16) ? 8 : 0;

#pragma unroll 1
    for (int p = 0; p < KTOT; p++) {
        if (p < KTOT - 1) { stage(p + 1, (p + 1) & 1); CP_COMMIT(); CP_WAIT1(); }
        else              { CP_WAIT0(); }
        __syncthreads();

        char* hbuf = smem + SM_U0 + (p & 1) * UB_BYTES;
        char* lbuf = hbuf + UB_PLANE;
        int rowA = w * 16 + lr + rsel;
#pragma unroll
        for (int kl = 0; kl < 4; kl++) {
            int colA = kl * 16 + csel;
            uint32_t ah[4], al[4];
            ldm_x4(ah, smem_u32(hbuf + rowA * 144 + colA * 2));
            ldm_x4(al, smem_u32(lbuf + rowA * 144 + colA * 2));
            int kk = p * 4 + kl;
#pragma unroll
            for (int oc = 0; oc < 8; oc++) {
                uint2 wh = wf[((0 * 20 + kk) * 8 + oc) * 32 + lane];
                uint2 wl = wf[((1 * 20 + kk) * 8 + oc) * 32 + lane];
                mma16816(acc[oc], ah, wh.x, wh.y);
                mma16816(acc[oc], ah, wl.x, wl.y);
                mma16816(acc[oc], al, wh.x, wh.y);
            }
        }
        __syncthreads();
    }

    // epilogue: transpose D through smem (reuse phase buffer 0) -> coalesced y
    float* dout = reinterpret_cast<float*>(smem + SM_U0);   // [64][132]
    int g = lane >> 2, tg = lane & 3;
#pragma unroll
    for (int oc = 0; oc < 8; oc++) {
        int o = oc * 8 + 2 * tg;
        int ml = w * 16 + g;
        dout[o * 132 + ml]           = acc[oc][0];
        dout[(o + 1) * 132 + ml]     = acc[oc][1];
        dout[o * 132 + ml + 8]       = acc[oc][2];
        dout[(o + 1) * 132 + ml + 8] = acc[oc][3];
    }
    __syncthreads();

    int o = t >> 2, q = t & 3;
    float bv = __ldg(bias + o);
    float* yrow = y + ((size_t)b * 64 + o) * MM;
#pragma unroll
    for (int i = 0; i < 8; i++) {
        int c4 = q + i * 4;               // float4 index 0..31
        int m = mBase + c4 * 4;
        float4 v = *reinterpret_cast<float4*>(dout + o * 132 + c4 * 4);
        v.x += bv; v.y += bv; v.z += bv; v.w += bv;
        if (m + 3 < MM) {
            *reinterpret_cast<float4*>(yrow + m) = v;
        } else {
            if (m     < MM) yrow[m]     = v.x;
            if (m + 1 < MM) yrow[m + 1] = v.y;
            if (m + 2 < MM) yrow[m + 2] = v.z;
            if (m + 3 < MM) yrow[m + 3] = v.w;
        }
    }
}

// ---------------- launch ----------------------------------------------------
extern "C" void kernel_launch(void* const* d_in, const int* in_sizes, int n_in,
                              void* d_out, int out_size) {
    const int*   LlI  = (const int*)  d_in[0];
    const float* LlV  = (const float*)d_in[1];
    const int*   LuI  = (const int*)  d_in[2];
    const float* LuV  = (const float*)d_in[3];
    const float* x    = (const float*)d_in[4];
    const float* th   = (const float*)d_in[5];
    const float* bias = (const float*)d_in[6];
    float*       y    = (float*)d_out;
    int nnz = in_sizes[1];

    float *xt, *p1l, *p1u;
    uint16_t* ubf;
    uint2* wfrag;
    cudaGetSymbolAddress((void**)&xt,    g_xt);
    cudaGetSymbolAddress((void**)&p1l,   g_p1l);
    cudaGetSymbolAddress((void**)&p1u,   g_p1u);
    cudaGetSymbolAddress((void**)&ubf,   g_ubf);
    cudaGetSymbolAddress((void**)&wfrag, g_wfrag);

    int  *cnt;
    int2 *ents;
    cudaGetSymbolAddress((void**)&cnt,  g_cnt);
    cudaGetSymbolAddress((void**)&ents, g_ents);

    cudaMemsetAsync(cnt, 0, 2 * MM * sizeof(int));

    int eb2 = (2 * nnz + 255) / 256;
    scatter_ell_kernel<<<eb2, 256>>>(LlI, LuI, LlV, LuV, cnt, ents, nnz);

    transpose_kernel<<<dim3(MM / 32, NF / 32), dim3(32, 8)>>>(x, xt);
    wprep_kernel<<<(2 * 20 * 8 * 32 + 255) / 256, 256>>>(th, wfrag);

    int spmmBlocks = (2 * MM * 32 + 255) / 256;
    // pass A: p1 = L*xt (fp32 + bf16 slots 1,3)
    spmm_dual_kernel<<<spmmBlocks, 256>>>(cnt, ents, xt, xt, p1l, p1u,
                                          ubf + 1 * UBF_SLOT, ubf + 3 * UBF_SLOT);
    // pass B: p2 = L*p1 (bf16 only, slots 2,4)
    spmm_dual_kernel<<<spmmBlocks, 256>>>(cnt, ents, p1l, p1u, nullptr, nullptr,
                                          ubf + 2 * UBF_SLOT, ubf + 4 * UBF_SLOT);

    cudaFuncSetAttribute(combine_kernel,
                         cudaFuncAttributeMaxDynamicSharedMemorySize, CMB_SMEM_BYTES);
    combine_kernel<<<dim3((MM + 127) / 128, 2), CMB_THREADS, CMB_SMEM_BYTES>>>(bias, y);
}

// round 10
// speedup vs baseline: 3.1586x; 1.1431x over previous
#include <cuda_runtime.h>
#include <cuda_bf16.h>
#include <cstdint>

#define MM    100000   // simplices
#define KTOT  5        // [x, Ll x, Ll^2 x, Lu x, Lu^2 x]
#define ELLW  48       // ELL row capacity
// ubf slot: per m, 32 groups x 16B; group g = [hi ch4g..4g+3 (8B) | lo (8B)]
#define UBF_SLOT ((size_t)MM * 256)   // uint16 elems per k-slot (512 B/row)

// ---------------- scratch (device globals: no allocations allowed) ----------
__device__ __align__(16) uint16_t g_ubf[(size_t)KTOT * MM * 256];  // 256MB
__device__ __align__(16) uint2    g_wfrag[2 * 20 * 8 * 32];        // B frags, 80KB
__device__ int   g_cnt [2 * MM];
__device__ __align__(16) int2 g_ents[(size_t)2 * MM * ELLW];

// ---------------- helpers ----------------------------------------------------
__device__ __forceinline__ uint32_t smem_u32(const void* p) {
    uint32_t a;
    asm("{ .reg .u64 t; cvta.to.shared.u64 t, %1; cvt.u32.u64 %0, t; }"
        : "=r"(a) : "l"(p));
    return a;
}
__device__ __forceinline__ void cp_async8(uint32_t dst, const void* src, int szr) {
    asm volatile("cp.async.ca.shared.global [%0], [%1], 8, %2;"
                 :: "r"(dst), "l"(src), "r"(szr));
}
#define CP_COMMIT() asm volatile("cp.async.commit_group;" ::: "memory")
#define CP_WAIT1()  asm volatile("cp.async.wait_group 1;" ::: "memory")
#define CP_WAIT0()  asm volatile("cp.async.wait_group 0;" ::: "memory")

__device__ __forceinline__ void ldm_x4(uint32_t* r, uint32_t addr) {
    asm volatile("ldmatrix.sync.aligned.m8n8.x4.shared.b16 {%0,%1,%2,%3}, [%4];"
                 : "=r"(r[0]), "=r"(r[1]), "=r"(r[2]), "=r"(r[3]) : "r"(addr));
}
__device__ __forceinline__ void mma16816(float* c, const uint32_t* a,
                                         uint32_t b0, uint32_t b1) {
    asm volatile("mma.sync.aligned.m16n8k16.row.col.f32.bf16.bf16.f32 "
                 "{%0,%1,%2,%3}, {%4,%5,%6,%7}, {%8,%9}, {%0,%1,%2,%3};"
                 : "+f"(c[0]), "+f"(c[1]), "+f"(c[2]), "+f"(c[3])
                 : "r"(a[0]), "r"(a[1]), "r"(a[2]), "r"(a[3]), "r"(b0), "r"(b1));
}
__device__ __forceinline__ uint16_t bf_bits(__nv_bfloat16 h) {
    return *reinterpret_cast<uint16_t*>(&h);
}
__device__ __forceinline__ float2 bf2f(uint32_t u) {
    __nv_bfloat162 h = *reinterpret_cast<__nv_bfloat162*>(&u);
    return __bfloat1622float2(h);
}
// accumulate v * (hi+lo) for one interleaved uint4 (4 channels)
__device__ __forceinline__ void acc4(float& ax, float& ay, float& az, float& aw,
                                     uint4 g, float v) {
    float2 h01 = bf2f(g.x), h23 = bf2f(g.y);
    float2 l01 = bf2f(g.z), l23 = bf2f(g.w);
    ax += v * (h01.x + l01.x); ay += v * (h01.y + l01.y);
    az += v * (h23.x + l23.x); aw += v * (h23.y + l23.y);
}

// ---------------- 1) transpose x (128, M) -> ubf slot 0 (hi/lo interleave) --
__global__ void transpose_kernel(const float* __restrict__ x) {
    __shared__ float tile[32][33];
    int mBase = blockIdx.x * 32, fBase = blockIdx.y * 32;
    int tx = threadIdx.x, ty = threadIdx.y;
#pragma unroll
    for (int i = 0; i < 32; i += 8)
        tile[ty + i][tx] = x[(size_t)(fBase + ty + i) * MM + mBase + tx];
    __syncthreads();
    uint16_t* ub = g_ubf;
#pragma unroll
    for (int i = 0; i < 32; i += 8) {
        float v = tile[tx][ty + i];
        int m = mBase + ty + i, f = fBase + tx;
        __nv_bfloat16 h = __float2bfloat16_rn(v);
        __nv_bfloat16 l = __float2bfloat16_rn(v - __bfloat162float(h));
        size_t base = (size_t)m * 256 + (size_t)(f >> 2) * 8 + (f & 3);
        ub[base]     = bf_bits(h);     // hi half of group
        ub[base + 4] = bf_bits(l);     // lo half of group
    }
}

// ---------------- ELL build ---------------------------------------------------
__global__ void scatter_ell_kernel(const int* __restrict__ LlI, const int* __restrict__ LuI,
                                   const float* __restrict__ LlV, const float* __restrict__ LuV,
                                   int* __restrict__ cnt, int2* __restrict__ ents, int nnz) {
    int e = blockIdx.x * blockDim.x + threadIdx.x;
    if (e >= 2 * nnz) return;
    int s = (e >= nnz);
    int el = e - s * nnz;
    int r   = s ? LuI[el]       : LlI[el];
    int c   = s ? LuI[el + nnz] : LlI[el + nnz];
    float v = s ? LuV[el]       : LlV[el];
    int idx = atomicAdd(&cnt[s * MM + r], 1);
    if (idx < ELLW)
        ents[(size_t)(s * MM + r) * ELLW + idx] = make_int2(c, __float_as_int(v));
}

// ---------------- 2) dual ELL SpMM: bf16 hi/lo in, bf16 hi/lo out ------------
__global__ void spmm_dual_kernel(const int* __restrict__ cnt, const int2* __restrict__ entsB,
                                 const uint4* __restrict__ in0, const uint4* __restrict__ in1,
                                 uint4* __restrict__ ob0, uint4* __restrict__ ob1) {
    int w = (blockIdx.x * blockDim.x + threadIdx.x) >> 5;
    if (w >= 2 * MM) return;
    int s = (w >= MM);
    int r = w - s * MM;
    int lane = threadIdx.x & 31;
    const uint4* in = s ? in1 : in0;

    int n = __ldg(cnt + s * MM + r);
    n = n < ELLW ? n : ELLW;
    const int2* ents = entsB + (size_t)(s * MM + r) * ELLW;
    int j = 0;
    float ax = 0.f, ay = 0.f, az = 0.f, aw = 0.f;

    for (; n >= 4; n -= 4, j += 4) {
        int2 e0 = __ldg(ents + j);
        int2 e1 = __ldg(ents + j + 1);
        int2 e2 = __ldg(ents + j + 2);
        int2 e3 = __ldg(ents + j + 3);
        uint4 g0 = __ldg(in + (size_t)e0.x * 32 + lane);
        uint4 g1 = __ldg(in + (size_t)e1.x * 32 + lane);
        uint4 g2 = __ldg(in + (size_t)e2.x * 32 + lane);
        uint4 g3 = __ldg(in + (size_t)e3.x * 32 + lane);
        acc4(ax, ay, az, aw, g0, __int_as_float(e0.y));
        acc4(ax, ay, az, aw, g1, __int_as_float(e1.y));
        acc4(ax, ay, az, aw, g2, __int_as_float(e2.y));
        acc4(ax, ay, az, aw, g3, __int_as_float(e3.y));
    }
    for (; n > 0; n--, j++) {
        int2 ev = __ldg(ents + j);
        uint4 g = __ldg(in + (size_t)ev.x * 32 + lane);
        acc4(ax, ay, az, aw, g, __int_as_float(ev.y));
    }

    // hi/lo split, interleaved store (group = lane)
    __nv_bfloat162 h01 = __floats2bfloat162_rn(ax, ay);
    __nv_bfloat162 h23 = __floats2bfloat162_rn(az, aw);
    float2 f01 = __bfloat1622float2(h01);
    float2 f23 = __bfloat1622float2(h23);
    __nv_bfloat162 l01 = __floats2bfloat162_rn(ax - f01.x, ay - f01.y);
    __nv_bfloat162 l23 = __floats2bfloat162_rn(az - f23.x, aw - f23.y);
    uint4 o;
    o.x = *reinterpret_cast<uint32_t*>(&h01);
    o.y = *reinterpret_cast<uint32_t*>(&h23);
    o.z = *reinterpret_cast<uint32_t*>(&l01);
    o.w = *reinterpret_cast<uint32_t*>(&l23);
    (s ? ob1 : ob0)[(size_t)r * 32 + lane] = o;
}

// ---------------- 3) fold theta -> B fragments (mma register order) ---------
__global__ void wprep_kernel(const float* __restrict__ theta, uint2* __restrict__ wfrag) {
    int i = blockIdx.x * blockDim.x + threadIdx.x;
    if (i >= 2 * 20 * 8 * 32) return;
    int lane = i & 31;
    int oc   = (i >> 5) & 7;
    int kk   = (i >> 8) % 20;
    int part = i / 5120;
    int tg = lane & 3, g = lane >> 2;
    int o = oc * 8 + g;
    const int kmap[KTOT] = {0, 1, 2, 4, 5};
    uint16_t bits[4];
#pragma unroll
    for (int e = 0; e < 4; e++) {
        int j = kk * 16 + 2 * tg + (e & 1) + (e >> 1) * 8;
        int kb = j >> 6, c = j & 63;
        float f = theta[(o * 64 + c) * 6 + kmap[kb]];
        if (kb == 0) f += theta[(o * 64 + c) * 6 + 3];
        __nv_bfloat16 h = __float2bfloat16_rn(f);
        if (part == 0) bits[e] = bf_bits(h);
        else           bits[e] = bf_bits(__float2bfloat16_rn(f - __bfloat162float(h)));
    }
    wfrag[i] = make_uint2((uint32_t)bits[0] | ((uint32_t)bits[1] << 16),
                          (uint32_t)bits[2] | ((uint32_t)bits[3] << 16));
}

// ---------------- 4) combine: warp-level bf16 MMA ----------------------------
// CTA: 256 thr (8 warps), tile 128m x 64o, batch b. Warp w: m-rows w*16..+15.
// Stage de-interleaves hi/lo planes via 8B cp.async.
#define CMB_THREADS 256
#define SM_WF    0
#define WF_BYTES 81920
#define UB_PLANE 18432                  // 128 rows * 144B (64ch + pad)
#define UB_BYTES (2 * UB_PLANE)         // hi + lo planes
#define SM_U0    WF_BYTES
#define CMB_SMEM_BYTES (WF_BYTES + 2 * UB_BYTES)   // 155648

__global__ __launch_bounds__(CMB_THREADS, 1)
void combine_kernel(const float* __restrict__ bias, float* __restrict__ y) {
    extern __shared__ char smem[];
    int t = threadIdx.x;
    int lane = t & 31, w = t >> 5;
    int b = blockIdx.y;
    int mBase = blockIdx.x * 128;

    // stage W fragments (80KB)
    {
        const float4* src = reinterpret_cast<const float4*>(g_wfrag);
        float4* dst = reinterpret_cast<float4*>(smem + SM_WF);
#pragma unroll
        for (int i = t; i < WF_BYTES / 16; i += CMB_THREADS)
            dst[i] = src[i];
    }

    float acc[8][4];
#pragma unroll
    for (int oc = 0; oc < 8; oc++)
#pragma unroll
        for (int e = 0; e < 4; e++) acc[oc][e] = 0.f;

    // stage k-slot p: batch b channels = groups b*16..b*16+15.
    // dest chunk i (8B = ch 4i..4i+3 of the batch): src group b*16+i, plane*8.
    auto stage = [&](int p, int buf) {
        const char* srcb = reinterpret_cast<const char*>(g_ubf + (size_t)p * UBF_SLOT);
        char* dbase = smem + SM_U0 + buf * UB_BYTES;
#pragma unroll
        for (int jj = 0; jj < 16; jj++) {
            int idx = t + jj * CMB_THREADS;      // 0..4095
            int row = idx >> 5;
            int rem = idx & 31;
            int plane = rem >> 4, i = rem & 15;
            int mm = mBase + row;
            int ok = (mm < MM);
            const char* sp = srcb + (size_t)(ok ? mm : 0) * 512
                             + (b * 16 + i) * 16 + plane * 8;
            uint32_t d = smem_u32(dbase + plane * UB_PLANE + row * 144 + i * 8);
            cp_async8(d, sp, ok ? 8 : 0);
        }
    };

    stage(0, 0);
    CP_COMMIT();

    const uint2* wf = reinterpret_cast<const uint2*>(smem + SM_WF);
    int lr = lane & 7;
    int rsel = (lane & 8) ? 8 : 0;
    int csel = (lane & 16) ? 8 : 0;

#pragma unroll 1
    for (int p = 0; p < KTOT; p++) {
        if (p < KTOT - 1) { stage(p + 1, (p + 1) & 1); CP_COMMIT(); CP_WAIT1(); }
        else              { CP_WAIT0(); }
        __syncthreads();

        char* hbuf = smem + SM_U0 + (p & 1) * UB_BYTES;
        char* lbuf = hbuf + UB_PLANE;
        int rowA = w * 16 + lr + rsel;
#pragma unroll
        for (int kl = 0; kl < 4; kl++) {
            int colA = kl * 16 + csel;
            uint32_t ah[4], al[4];
            ldm_x4(ah, smem_u32(hbuf + rowA * 144 + colA * 2));
            ldm_x4(al, smem_u32(lbuf + rowA * 144 + colA * 2));
            int kk = p * 4 + kl;
#pragma unroll
            for (int oc = 0; oc < 8; oc++) {
                uint2 wh = wf[((0 * 20 + kk) * 8 + oc) * 32 + lane];
                uint2 wl = wf[((1 * 20 + kk) * 8 + oc) * 32 + lane];
                mma16816(acc[oc], ah, wh.x, wh.y);
                mma16816(acc[oc], ah, wl.x, wl.y);
                mma16816(acc[oc], al, wh.x, wh.y);
            }
        }
        __syncthreads();
    }

    // epilogue: transpose D through smem -> coalesced y
    float* dout = reinterpret_cast<float*>(smem + SM_U0);   // [64][132]
    int g = lane >> 2, tg = lane & 3;
#pragma unroll
    for (int oc = 0; oc < 8; oc++) {
        int o = oc * 8 + 2 * tg;
        int ml = w * 16 + g;
        dout[o * 132 + ml]           = acc[oc][0];
        dout[(o + 1) * 132 + ml]     = acc[oc][1];
        dout[o * 132 + ml + 8]       = acc[oc][2];
        dout[(o + 1) * 132 + ml + 8] = acc[oc][3];
    }
    __syncthreads();

    int o = t >> 2, q = t & 3;
    float bv = __ldg(bias + o);
    float* yrow = y + ((size_t)b * 64 + o) * MM;
#pragma unroll
    for (int i = 0; i < 8; i++) {
        int c4 = q + i * 4;
        int m = mBase + c4 * 4;
        float4 v = *reinterpret_cast<float4*>(dout + o * 132 + c4 * 4);
        v.x += bv; v.y += bv; v.z += bv; v.w += bv;
        if (m + 3 < MM) {
            *reinterpret_cast<float4*>(yrow + m) = v;
        } else {
            if (m     < MM) yrow[m]     = v.x;
            if (m + 1 < MM) yrow[m + 1] = v.y;
            if (m + 2 < MM) yrow[m + 2] = v.z;
            if (m + 3 < MM) yrow[m + 3] = v.w;
        }
    }
}

// ---------------- launch ----------------------------------------------------
extern "C" void kernel_launch(void* const* d_in, const int* in_sizes, int n_in,
                              void* d_out, int out_size) {
    const int*   LlI  = (const int*)  d_in[0];
    const float* LlV  = (const float*)d_in[1];
    const int*   LuI  = (const int*)  d_in[2];
    const float* LuV  = (const float*)d_in[3];
    const float* x    = (const float*)d_in[4];
    const float* th   = (const float*)d_in[5];
    const float* bias = (const float*)d_in[6];
    float*       y    = (float*)d_out;
    int nnz = in_sizes[1];

    uint16_t* ubf;
    uint2* wfrag;
    cudaGetSymbolAddress((void**)&ubf,   g_ubf);
    cudaGetSymbolAddress((void**)&wfrag, g_wfrag);

    int  *cnt;
    int2 *ents;
    cudaGetSymbolAddress((void**)&cnt,  g_cnt);
    cudaGetSymbolAddress((void**)&ents, g_ents);

    cudaMemsetAsync(cnt, 0, 2 * MM * sizeof(int));

    int eb2 = (2 * nnz + 255) / 256;
    scatter_ell_kernel<<<eb2, 256>>>(LlI, LuI, LlV, LuV, cnt, ents, nnz);

    transpose_kernel<<<dim3(MM / 32, 4), dim3(32, 8)>>>(x);
    wprep_kernel<<<(2 * 20 * 8 * 32 + 255) / 256, 256>>>(th, wfrag);

    uint4* slot0 = reinterpret_cast<uint4*>(ubf);
    uint4* slot1 = reinterpret_cast<uint4*>(ubf + 1 * UBF_SLOT);
    uint4* slot2 = reinterpret_cast<uint4*>(ubf + 2 * UBF_SLOT);
    uint4* slot3 = reinterpret_cast<uint4*>(ubf + 3 * UBF_SLOT);
    uint4* slot4 = reinterpret_cast<uint4*>(ubf + 4 * UBF_SLOT);

    int spmmBlocks = (2 * MM * 32 + 255) / 256;
    spmm_dual_kernel<<<spmmBlocks, 256>>>(cnt, ents, slot0, slot0, slot1, slot3);
    spmm_dual_kernel<<<spmmBlocks, 256>>>(cnt, ents, slot1, slot3, slot2, slot4);

    cudaFuncSetAttribute(combine_kernel,
                         cudaFuncAttributeMaxDynamicSharedMemorySize, CMB_SMEM_BYTES);
    combine_kernel<<<dim3((MM + 127) / 128, 2), CMB_THREADS, CMB_SMEM_BYTES>>>(bias, y);
}